// round 2
// baseline (speedup 1.0000x reference)
#include <cuda_runtime.h>
#include <math.h>

#define NB 8
#define NA 128
#define NE (NA*(NA-1))   // 16256
#define NL 9
#define NF 64
#define NK 16
#define LF (NL*NF)       // 576
#define LK (NL*NK)       // 144
#define SQ3f 1.7320508075688772f
#define CUT2 25.0f

// ------------------ scratch (static device globals; no allocs) ------------------
__device__ float d_B [(size_t)NB*NE*LK];   // basis per edge
__device__ float d_gB[(size_t)NB*NE*LK];   // grad wrt basis
__device__ int   d_act[NB*NE];
__device__ float d_x0[(size_t)NB*NA*LF];
__device__ float d_x1[(size_t)NB*NA*LF];
__device__ float d_x2[(size_t)NB*NA*LF];
__device__ float d_y1buf[(size_t)NB*NA*LF];
__device__ float d_y2a[(size_t)NB*NA*LF];  // saved pre-gating y2, layer 0
__device__ float d_y2b[(size_t)NB*NA*LF];  // layer 1
__device__ float d_yF[NB*NA*NF];
__device__ float d_dh0[NB*NA*NF];
__device__ float d_gxA[(size_t)NB*NA*LF];  // grad wrt x2
__device__ float d_gxB[(size_t)NB*NA*LF];  // grad wrt x1
__device__ float d_gy1[(size_t)NB*NA*LF];
__device__ float d_dd[(size_t)NB*NE*3];    // per-edge ddisp
__device__ float d_ae[NB*NA];

__constant__ int   c_deg[9]    = {0,1,1,1,2,2,2,2,2};
__constant__ float c_binom[16] = {1.f,15.f,105.f,455.f,1365.f,3003.f,5005.f,6435.f,
                                  6435.f,5005.f,3003.f,1365.f,455.f,105.f,15.f,1.f};

// ------------------ forward: edge basis ------------------
__global__ void k_basis(const float* __restrict__ pos){
    int gid = blockIdx.x*blockDim.x + threadIdx.x;
    if(gid >= NB*NE) return;
    int b = gid / NE, e = gid % NE;
    int dst = e / (NA-1), s = e % (NA-1);
    int src = (s < dst) ? s : s+1;
    const float* pd = pos + (b*NA+dst)*3;
    const float* ps = pos + (b*NA+src)*3;
    float dx=ps[0]-pd[0], dy=ps[1]-pd[1], dz=ps[2]-pd[2];
    float r2 = dx*dx+dy*dy+dz*dz + 1e-12f;
    float om = 1.f - r2/CUT2;
    if(om <= 1e-6f){ d_act[gid]=0; return; }
    d_act[gid]=1;
    float r = sqrtf(r2), inv_r = 1.f/r;
    float ux=dx*inv_r, uy=dy*inv_r, uz=dz*inv_r;
    float Y[9];
    Y[0]=1.f; Y[1]=ux; Y[2]=uy; Y[3]=uz;
    Y[4]=SQ3f*ux*uy; Y[5]=SQ3f*uy*uz; Y[6]=0.5f*(3.f*uz*uz-1.f);
    Y[7]=SQ3f*ux*uz; Y[8]=0.5f*SQ3f*(ux*ux-uy*uy);
    float w = 1.f/(1.f+r), v = 1.f-w;
    float cut = expf(1.f - 1.f/om);
    float vp[16]; vp[0]=1.f;
    #pragma unroll
    for(int j=1;j<16;j++) vp[j]=vp[j-1]*v;
    float rad[16]; float wk=1.f;
    #pragma unroll
    for(int k=0;k<16;k++){ rad[k]=c_binom[k]*wk*vp[15-k]; wk*=w; }
    float* Bo = d_B + (size_t)gid*LK;
    #pragma unroll
    for(int l=0;l<9;l++){
        float yc = Y[l]*cut;
        #pragma unroll
        for(int k=0;k<16;k++) Bo[l*16+k] = yc*rad[k];
    }
}

// ------------------ forward: embed init ------------------
__global__ void k_init(const int* __restrict__ z, const float* __restrict__ embed){
    int bn = blockIdx.x; int b=bn/NA, n=bn%NA;
    int f = threadIdx.x;
    float* x = d_x0 + (size_t)bn*LF;
    x[f] = embed[z[b*NA+n]*NF + f];
    #pragma unroll
    for(int l=1;l<9;l++) x[l*NF+f]=0.f;
}

// ------------------ forward: layer message + aggregate -> y1 ------------------
__global__ void k_msg(const float* __restrict__ WA, const float* __restrict__ WB, int layer){
    int bn = blockIdx.x; int b=bn/NA, n=bn%NA;
    int t = threadIdx.x; int l=t/NF, f=t%NF;
    const float* xin = layer ? d_x1 : d_x0;
    __shared__ float sWA[NK*NF], sWB[NK*NF], sB[LK], sxs[LF];
    __shared__ int sact[NA-1];
    for(int i=t;i<NK*NF;i+=LF){ sWA[i]=WA[i]; sWB[i]=WB[i]; }
    if(t<NA-1) sact[t] = d_act[b*NE + n*(NA-1)+t];
    float acc = xin[(size_t)bn*LF + t];
    __syncthreads();
    for(int ei=0; ei<NA-1; ++ei){
        if(!sact[ei]) continue;
        int src = (ei<n)? ei : ei+1;
        size_t e = (size_t)b*NE + n*(NA-1)+ei;
        if(t<LK) sB[t]=d_B[e*LK+t];
        sxs[t] = xin[((size_t)b*NA+src)*LF + t];
        __syncthreads();
        float A=0.f, s0=0.f;
        #pragma unroll
        for(int k=0;k<NK;k++){ A += sB[l*NK+k]*sWA[k*NF+f]; s0 += sB[k]*sWB[k*NF+f]; }
        acc += A*sxs[f] + sxs[t]*s0;
        __syncthreads();
    }
    d_y1buf[(size_t)bn*LF+t] = acc;
}

// ------------------ forward: node update (W1, gating, W2, residual) ------------------
__global__ void k_node(const float* __restrict__ W1, const float* __restrict__ b1,
                       const float* __restrict__ W2, int layer){
    int bn = blockIdx.x;
    int t = threadIdx.x; int l=t/NF, g=t%NF;
    int deg = c_deg[l];
    const float* xin  = layer ? d_x1 : d_x0;
    float* xout = layer ? d_x2 : d_x1;
    float* y2out= layer ? d_y2b : d_y2a;
    __shared__ float sy1[LF], sy2[LF], sy3[LF];
    size_t base = (size_t)bn*LF;
    sy1[t] = d_y1buf[base+t];
    __syncthreads();
    const float* w1 = W1 + deg*4096;
    float v = 0.f;
    for(int f=0; f<NF; f++) v += sy1[l*NF+f]*w1[f*NF+g];
    if(l==0) v += b1[g];
    sy2[t]=v; y2out[base+t]=v;
    __syncthreads();
    float s = sy2[g];                 // y2[0,g]
    float sig = 1.f/(1.f+expf(-s));
    float y3 = (l==0) ? s*sig : v*sig;
    sy3[t]=y3;
    __syncthreads();
    const float* w2 = W2 + deg*4096;
    float o = 0.f;
    for(int f=0; f<NF; f++) o += sy3[l*NF+f]*w2[f*NF+g];
    xout[base+t] = xin[base+t] + o;
}

// ------------------ forward: final edge messages -> yF ------------------
__global__ void k_final_edge(const float* __restrict__ WA2, const float* __restrict__ WB2){
    int bn = blockIdx.x; int b=bn/NA, n=bn%NA;
    int t = threadIdx.x; int l=t/NF, f=t%NF;
    __shared__ float sWA[NK*NF], sWB[NK*NF], sB[LK], sxs[LF], sred[LF];
    __shared__ int sact[NA-1];
    for(int i=t;i<NK*NF;i+=LF){ sWA[i]=WA2[i]; sWB[i]=WB2[i]; }
    if(t<NA-1) sact[t] = d_act[b*NE + n*(NA-1)+t];
    float acc=0.f;
    __syncthreads();
    for(int ei=0; ei<NA-1; ++ei){
        if(!sact[ei]) continue;
        int src = (ei<n)? ei : ei+1;
        size_t e = (size_t)b*NE + n*(NA-1)+ei;
        if(t<LK) sB[t]=d_B[e*LK+t];
        sxs[t] = d_x2[((size_t)b*NA+src)*LF + t];
        __syncthreads();
        float sbw=0.f;
        #pragma unroll
        for(int k=0;k<NK;k++) sbw += sB[l*NK+k]*sWB[k*NF+f];
        float c = sxs[t]*sbw;
        if(l==0){
            float a2=0.f;
            #pragma unroll
            for(int k=0;k<NK;k++) a2 += sB[k]*sWA[k*NF+f];
            c += a2*sxs[f];
        }
        acc += c;
        __syncthreads();
    }
    sred[t]=acc;
    __syncthreads();
    if(l==0){
        float ss=0.f;
        #pragma unroll
        for(int l2=0;l2<NL;l2++) ss += sred[l2*NF+f];
        d_yF[bn*NF+f]=ss;
    }
}

// ------------------ forward+backward: final scalar MLP, energy, gx2 init ------------------
__global__ void k_final_node(const int* __restrict__ z,
                             const float* __restrict__ W1s, const float* __restrict__ b1s,
                             const float* __restrict__ W2s, const float* __restrict__ w_out,
                             const float* __restrict__ ebias){
    int bn = blockIdx.x; int b=bn/NA, n=bn%NA;
    int f = threadIdx.x; // 64
    __shared__ float sh0[NF], sq[NF], sdp[NF], sred[NF];
    size_t base = (size_t)bn*LF;
    float x0 = d_x2[base + f];
    float h0 = x0 + d_yF[bn*NF+f];
    sh0[f]=h0; __syncthreads();
    float p = b1s[f];
    for(int g=0; g<NF; g++) p += sh0[g]*W1s[g*NF+f];
    float sig = 1.f/(1.f+expf(-p));
    float q = p*sig;
    sq[f]=q; __syncthreads();
    float hh=0.f;
    for(int g=0; g<NF; g++) hh += sq[g]*W2s[g*NF+f];
    float xo = x0 + hh;
    sred[f]=xo*w_out[f]; __syncthreads();
    for(int s=32;s>0;s>>=1){ if(f<s) sred[f]+=sred[f+s]; __syncthreads(); }
    if(f==0) d_ae[bn] = sred[0] + ebias[z[b*NA+n]];
    // backward (dE/dE = 1)
    float dq=0.f;
    for(int g=0; g<NF; g++) dq += w_out[g]*W2s[f*NF+g];
    float dp = dq * sig*(1.f + p*(1.f-sig));
    sdp[f]=dp; __syncthreads();
    float dh0=0.f;
    for(int g=0; g<NF; g++) dh0 += sdp[g]*W1s[f*NF+g];
    d_dh0[bn*NF+f] = dh0;
    float* gx = d_gxA + base;
    gx[f] = w_out[f] + dh0;      // grad into x2[:,0,:] (direct + through h0)
    #pragma unroll
    for(int l=1;l<9;l++) gx[l*NF+f]=0.f;
}

__global__ void k_energy(float* __restrict__ out){
    int b = blockIdx.x;
    __shared__ float sh[NA];
    sh[threadIdx.x]=d_ae[b*NA+threadIdx.x];
    __syncthreads();
    for(int s=64;s>0;s>>=1){ if(threadIdx.x<s) sh[threadIdx.x]+=sh[threadIdx.x+s]; __syncthreads(); }
    if(threadIdx.x==0) out[b]=sh[0];
}

// ------------------ backward: final edge (writes gB '=', gathers into gxA) ------------------
__global__ void kb_final_edge(const float* __restrict__ WA2, const float* __restrict__ WB2){
    int bn = blockIdx.x; int b=bn/NA, j=bn%NA;
    int t = threadIdx.x; int l=t/NF, f=t%NF;
    __shared__ float sWA[NK*NF], sWB[NK*NF], sB[LK], sxs[LF], sdm[NF];
    for(int i=t;i<NK*NF;i+=LF){ sWA[i]=WA2[i]; sWB[i]=WB2[i]; }
    sxs[t] = d_x2[(size_t)bn*LF + t];
    float acc=0.f;
    __syncthreads();
    for(int i=0;i<NA;i++){
        if(i==j) continue;
        int e = b*NE + i*(NA-1) + ((j<i)? j : j-1);
        if(!d_act[e]) continue;
        if(t<LK) sB[t]=d_B[(size_t)e*LK+t];
        if(t<NF) sdm[t]=d_dh0[(b*NA+i)*NF+t];
        __syncthreads();
        float sbw=0.f;
        #pragma unroll
        for(int k=0;k<NK;k++) sbw += sB[l*NK+k]*sWB[k*NF+f];
        acc += sdm[f]*sbw;
        if(l==0){
            float a2=0.f;
            #pragma unroll
            for(int k=0;k<NK;k++) a2 += sB[k]*sWA[k*NF+f];
            acc += sdm[f]*a2;
        }
        if(t<LK){
            int l2=t/NK, k=t%NK;
            float gg=0.f;
            const float* wb = sWB + k*NF;
            const float* xr = sxs + l2*NF;
            for(int ff=0; ff<NF; ff++) gg += sdm[ff]*wb[ff]*xr[ff];
            if(l2==0){
                const float* wa = sWA + k*NF;
                for(int ff=0; ff<NF; ff++) gg += sdm[ff]*sxs[ff]*wa[ff];
            }
            d_gB[(size_t)e*LK+t] = gg;   // first writer
        }
        __syncthreads();
    }
    d_gxA[(size_t)bn*LF+t] += acc;
}

// ------------------ backward: node update ------------------
__global__ void kb_node(const float* __restrict__ W1, const float* __restrict__ W2, int layer){
    int bn = blockIdx.x;
    int t = threadIdx.x; int l=t/NF, f=t%NF;
    int deg = c_deg[l];
    const float* gxin = (layer==1) ? d_gxA : d_gxB;
    const float* y2   = (layer==1) ? d_y2b : d_y2a;
    __shared__ float sgxo[LF], sy2[LF], sgy3[LF], sgy2[LF];
    size_t base=(size_t)bn*LF;
    sgxo[t]=gxin[base+t]; sy2[t]=y2[base+t];
    __syncthreads();
    const float* w2 = W2 + deg*4096 + f*NF;
    float gy3=0.f;
    for(int g=0; g<NF; g++) gy3 += sgxo[l*NF+g]*w2[g];
    sgy3[t]=gy3;
    __syncthreads();
    float s = sy2[f];
    float sig = 1.f/(1.f+expf(-s));
    float gy2;
    if(l==0){
        float a=0.f;
        #pragma unroll
        for(int l2=1;l2<NL;l2++) a += sgy3[l2*NF+f]*sy2[l2*NF+f];
        gy2 = gy3*sig*(1.f + s*(1.f-sig)) + a*sig*(1.f-sig);
    } else gy2 = gy3*sig;
    sgy2[t]=gy2;
    __syncthreads();
    const float* w1 = W1 + deg*4096 + f*NF;
    float gy1=0.f;
    for(int g=0; g<NF; g++) gy1 += sgy2[l*NF+g]*w1[g];
    d_gy1[base+t]=gy1;
    if(layer==1) d_gxB[base+t] = sgxo[t] + gy1;   // grad into x1 (residual + y1 direct)
}

// ------------------ backward: layer edge (gB +=, gather into gx_i) ------------------
__global__ void kb_edge(const float* __restrict__ WA, const float* __restrict__ WB, int layer){
    int bn = blockIdx.x; int b=bn/NA, j=bn%NA;
    int t = threadIdx.x; int l=t/NF, f=t%NF;
    const float* xin = layer ? d_x1 : d_x0;
    __shared__ float sWA[NK*NF], sWB[NK*NF], sB[LK], sxs[LF], sgm[LF], redA[LF], redS[LF], sgs0[NF];
    for(int i=t;i<NK*NF;i+=LF){ sWA[i]=WA[i]; sWB[i]=WB[i]; }
    sxs[t]=xin[(size_t)bn*LF+t];
    float acc=0.f;
    __syncthreads();
    for(int i=0;i<NA;i++){
        if(i==j) continue;
        int e = b*NE + i*(NA-1) + ((j<i)? j : j-1);
        if(!d_act[e]) continue;
        if(t<LK) sB[t]=d_B[(size_t)e*LK+t];
        sgm[t]=d_gy1[((size_t)b*NA+i)*LF+t];
        __syncthreads();
        float s0=0.f, A=0.f;
        #pragma unroll
        for(int k=0;k<NK;k++){ s0 += sB[k]*sWB[k*NF+f]; A += sB[l*NK+k]*sWA[k*NF+f]; }
        redA[t]=sgm[t]*A;
        redS[t]=sgm[t]*sxs[t];
        acc += sgm[t]*s0;
        __syncthreads();
        if(l==0){
            float sa=0.f, ss=0.f;
            #pragma unroll
            for(int l2=0;l2<NL;l2++){ sa+=redA[l2*NF+f]; ss+=redS[l2*NF+f]; }
            acc += sa;
            sgs0[f]=ss;
        }
        __syncthreads();
        if(t<LK){
            int l2=t/NK, k=t%NK;
            float gg=0.f;
            const float* wa = sWA + k*NF;
            for(int ff=0; ff<NF; ff++) gg += sgm[l2*NF+ff]*sxs[ff]*wa[ff];
            if(l2==0){
                const float* wb = sWB + k*NF;
                for(int ff=0; ff<NF; ff++) gg += sgs0[ff]*wb[ff];
            }
            d_gB[(size_t)e*LK+t] += gg;
        }
        __syncthreads();
    }
    if(layer==1) d_gxB[(size_t)bn*LF+t] += acc;   // layer0's gx0 is never used
}

// ------------------ backward: basis geometry -> per-edge ddisp ------------------
__global__ void k_ddisp(const float* __restrict__ pos){
    int gid = blockIdx.x*blockDim.x + threadIdx.x;
    if(gid >= NB*NE) return;
    float* dd = d_dd + (size_t)gid*3;
    if(!d_act[gid]){ dd[0]=0.f; dd[1]=0.f; dd[2]=0.f; return; }
    int b = gid/NE, e = gid%NE;
    int dst = e/(NA-1), s = e%(NA-1);
    int src = (s<dst)? s : s+1;
    const float* pd = pos + (b*NA+dst)*3;
    const float* ps = pos + (b*NA+src)*3;
    float dx=ps[0]-pd[0], dy=ps[1]-pd[1], dz=ps[2]-pd[2];
    float r2 = dx*dx+dy*dy+dz*dz+1e-12f;
    float r = sqrtf(r2), inv_r=1.f/r;
    float ux=dx*inv_r, uy=dy*inv_r, uz=dz*inv_r;
    float om = 1.f - r2/CUT2;
    float cut = expf(1.f - 1.f/om);
    float dcut = cut * (-2.f*r/CUT2)/(om*om);
    float w=1.f/(1.f+r), v=1.f-w, dwdr=-w*w;
    float wp[16], vp[16];
    wp[0]=1.f; vp[0]=1.f;
    #pragma unroll
    for(int i2=1;i2<16;i2++){ wp[i2]=wp[i2-1]*w; vp[i2]=vp[i2-1]*v; }
    float Y[9];
    Y[0]=1.f; Y[1]=ux; Y[2]=uy; Y[3]=uz;
    Y[4]=SQ3f*ux*uy; Y[5]=SQ3f*uy*uz; Y[6]=0.5f*(3.f*uz*uz-1.f);
    Y[7]=SQ3f*ux*uz; Y[8]=0.5f*SQ3f*(ux*ux-uy*uy);
    float rad[16], drd[16];
    #pragma unroll
    for(int k=0;k<16;k++){
        rad[k]=c_binom[k]*wp[k]*vp[15-k];
        float t1 = (k>0)  ? k*wp[k-1]*vp[15-k]       : 0.f;
        float t2 = (k<15) ? (15-k)*wp[k]*vp[14-k]    : 0.f;
        drd[k] = c_binom[k]*(t1-t2)*dwdr;
    }
    const float* g = d_gB + (size_t)gid*LK;
    float gY[9];
    #pragma unroll
    for(int l=0;l<9;l++){
        float sacc=0.f;
        #pragma unroll
        for(int k=0;k<16;k++) sacc += g[l*16+k]*rad[k];
        gY[l]=sacc*cut;
    }
    float gr=0.f;
    #pragma unroll
    for(int k=0;k<16;k++){
        float sacc=0.f;
        #pragma unroll
        for(int l=0;l<9;l++) sacc += g[l*16+k]*Y[l];
        gr += sacc*(drd[k]*cut + rad[k]*dcut);
    }
    float gux = gY[1] + SQ3f*(gY[4]*uy + gY[7]*uz + gY[8]*ux);
    float guy = gY[2] + SQ3f*(gY[4]*ux + gY[5]*uz - gY[8]*uy);
    float guz = gY[3] + SQ3f*(gY[5]*uy + gY[7]*ux) + 3.f*gY[6]*uz;
    float gd = gux*ux + guy*uy + guz*uz;
    dd[0] = (gux - gd*ux)*inv_r + gr*ux;
    dd[1] = (guy - gd*uy)*inv_r + gr*uy;
    dd[2] = (guz - gd*uz)*inv_r + gr*uz;
}

// ------------------ forces: deterministic per-atom gather ------------------
__global__ void k_force(float* __restrict__ out){
    int b = blockIdx.x; int a = threadIdx.x;
    const float* dd = d_dd + (size_t)b*NE*3;
    float fx=0.f, fy=0.f, fz=0.f;
    for(int ei=0; ei<NA-1; ++ei){      // edges with dst = a
        int e = a*(NA-1)+ei;
        fx += dd[e*3+0]; fy += dd[e*3+1]; fz += dd[e*3+2];
    }
    for(int i=0;i<NA;i++){             // edges with src = a
        if(i==a) continue;
        int e = i*(NA-1) + ((a<i)? a : a-1);
        fx -= dd[e*3+0]; fy -= dd[e*3+1]; fz -= dd[e*3+2];
    }
    float* F = out + NB + (size_t)(b*NA+a)*3;
    F[0]=fx; F[1]=fy; F[2]=fz;
}

// ------------------ launch ------------------
extern "C" void kernel_launch(void* const* d_in, const int* in_sizes, int n_in,
                              void* d_out, int out_size){
    const int*   z     = (const int*)  d_in[0];
    const float* pos   = (const float*)d_in[1];
    const float* embed = (const float*)d_in[2];
    const float* WA    = (const float*)d_in[3];
    const float* WB    = (const float*)d_in[4];
    const float* W1    = (const float*)d_in[5];
    const float* b1    = (const float*)d_in[6];
    const float* W2    = (const float*)d_in[7];
    const float* W1s   = (const float*)d_in[8];
    const float* b1s   = (const float*)d_in[9];
    const float* W2s   = (const float*)d_in[10];
    const float* w_out = (const float*)d_in[11];
    const float* ebias = (const float*)d_in[12];
    float* out = (float*)d_out;

    int eth = 256, ebl = (NB*NE + eth-1)/eth;

    k_basis<<<ebl, eth>>>(pos);
    k_init <<<NB*NA, NF>>>(z, embed);

    // layer 0
    k_msg  <<<NB*NA, LF>>>(WA + 0*NK*NF, WB + 0*NK*NF, 0);
    k_node <<<NB*NA, LF>>>(W1 + 0*3*4096, b1 + 0*NF, W2 + 0*3*4096, 0);
    // layer 1
    k_msg  <<<NB*NA, LF>>>(WA + 1*NK*NF, WB + 1*NK*NF, 1);
    k_node <<<NB*NA, LF>>>(W1 + 1*3*4096, b1 + 1*NF, W2 + 1*3*4096, 1);

    // final readout (fwd + local bwd)
    k_final_edge<<<NB*NA, LF>>>(WA + 2*NK*NF, WB + 2*NK*NF);
    k_final_node<<<NB*NA, NF>>>(z, W1s, b1s, W2s, w_out, ebias);
    k_energy    <<<NB, NA>>>(out);

    // backward through final edges -> gB (=), gx2
    kb_final_edge<<<NB*NA, LF>>>(WA + 2*NK*NF, WB + 2*NK*NF);

    // layer 1 backward
    kb_node<<<NB*NA, LF>>>(W1 + 1*3*4096, W2 + 1*3*4096, 1);
    kb_edge<<<NB*NA, LF>>>(WA + 1*NK*NF, WB + 1*NK*NF, 1);
    // layer 0 backward
    kb_node<<<NB*NA, LF>>>(W1 + 0*3*4096, W2 + 0*3*4096, 0);
    kb_edge<<<NB*NA, LF>>>(WA + 0*NK*NF, WB + 0*NK*NF, 0);

    // geometry backward + forces
    k_ddisp<<<ebl, eth>>>(pos);
    k_force<<<NB, NA>>>(out);
}

// round 3
// speedup vs baseline: 1.5574x; 1.5574x over previous
#include <cuda_runtime.h>
#include <math.h>

#define NB 8
#define NA 128
#define ND 127
#define NL 9
#define NF 64
#define NK 16
#define LF (NL*NF)       // 576
#define LK (NL*NK)       // 144
#define SK 17            // padded K-row stride
#define SF 65            // padded F-row stride
#define SQ3f 1.7320508075688772f
#define CUT2 25.0f
#define CH 4             // edge chunk

// ---------------- scratch ----------------
__device__ float d_Bc[(size_t)NB*NA*ND*LK];   // compacted basis
__device__ float d_gB[(size_t)NB*NA*ND*LK];   // compacted grad basis
__device__ float d_dd[(size_t)NB*NA*ND*3];
__device__ int   d_cnt [NB*NA];
__device__ int   d_rcnt[NB*NA];
__device__ int   d_nbr [NB*NA*NA];
__device__ int   d_slot[NB*NA*NA];
__device__ int   d_rnbr[NB*NA*NA];
__device__ int   d_redg[NB*NA*NA];
__device__ float d_x0[(size_t)NB*NA*LF];
__device__ float d_x1[(size_t)NB*NA*LF];
__device__ float d_x2[(size_t)NB*NA*LF];
__device__ float d_y1buf[(size_t)NB*NA*LF];
__device__ float d_y2a[(size_t)NB*NA*LF];
__device__ float d_y2b[(size_t)NB*NA*LF];
__device__ float d_yF[NB*NA*NF];
__device__ float d_dh0[NB*NA*NF];
__device__ float d_gxA[(size_t)NB*NA*LF];
__device__ float d_gxB[(size_t)NB*NA*LF];
__device__ float d_gy1[(size_t)NB*NA*LF];
__device__ float d_ae[NB*NA];

__constant__ int   c_deg[9]    = {0,1,1,1,2,2,2,2,2};
__constant__ float c_binom[16] = {1.f,15.f,105.f,455.f,1365.f,3003.f,5005.f,6435.f,
                                  6435.f,5005.f,3003.f,1365.f,455.f,105.f,15.f,1.f};

// ---------------- geometry + compaction + basis ----------------
__global__ void k_geom(const float* __restrict__ pos){
    int bn = blockIdx.x; int b=bn/NA, dst=bn%NA;
    int j = threadIdx.x;
    float pdx=pos[(b*NA+dst)*3+0], pdy=pos[(b*NA+dst)*3+1], pdz=pos[(b*NA+dst)*3+2];
    float dx=0.f,dy=0.f,dz=0.f,r2=1.f; bool act=false;
    if(j!=dst){
        dx=pos[(b*NA+j)*3+0]-pdx;
        dy=pos[(b*NA+j)*3+1]-pdy;
        dz=pos[(b*NA+j)*3+2]-pdz;
        r2=dx*dx+dy*dy+dz*dz+1e-12f;
        act = (1.f - r2/CUT2) > 1e-6f;
    }
    unsigned m=__ballot_sync(0xffffffffu, act);
    int wid=j>>5, lane=j&31;
    __shared__ int wcnt[4];
    if(lane==0) wcnt[wid]=__popc(m);
    __syncthreads();
    int basec=0;
    #pragma unroll
    for(int w=0;w<4;w++) if(w<wid) basec+=wcnt[w];
    int slot = basec + __popc(m & ((1u<<lane)-1u));
    if(j==0) d_cnt[bn]=wcnt[0]+wcnt[1]+wcnt[2]+wcnt[3];
    d_slot[bn*NA+j] = act ? slot : -1;
    if(!act) return;
    d_nbr[bn*NA+slot]=j;
    float om = 1.f - r2/CUT2;
    float r=sqrtf(r2), inv=1.f/r;
    float ux=dx*inv, uy=dy*inv, uz=dz*inv;
    float Y[9];
    Y[0]=1.f; Y[1]=ux; Y[2]=uy; Y[3]=uz;
    Y[4]=SQ3f*ux*uy; Y[5]=SQ3f*uy*uz; Y[6]=0.5f*(3.f*uz*uz-1.f);
    Y[7]=SQ3f*ux*uz; Y[8]=0.5f*SQ3f*(ux*ux-uy*uy);
    float w=1.f/(1.f+r), v=1.f-w;
    float cut=expf(1.f-1.f/om);
    float vp[16]; vp[0]=1.f;
    #pragma unroll
    for(int q=1;q<16;q++) vp[q]=vp[q-1]*v;
    float rad[16]; float wk=1.f;
    #pragma unroll
    for(int k=0;k<16;k++){ rad[k]=c_binom[k]*wk*vp[15-k]; wk*=w; }
    float4* Bo=(float4*)(d_Bc+((size_t)bn*ND+slot)*LK);
    #pragma unroll
    for(int l=0;l<9;l++){
        float yc=Y[l]*cut;
        #pragma unroll
        for(int q=0;q<4;q++)
            Bo[l*4+q]=make_float4(yc*rad[4*q],yc*rad[4*q+1],yc*rad[4*q+2],yc*rad[4*q+3]);
    }
}

__global__ void k_rev(){
    int bn=blockIdx.x; int b=bn/NA, j=bn%NA;
    int i=threadIdx.x;
    int s = (i!=j) ? d_slot[(b*NA+i)*NA + j] : -1;
    bool act = s>=0;
    unsigned m=__ballot_sync(0xffffffffu, act);
    int wid=i>>5, lane=i&31;
    __shared__ int wcnt[4];
    if(lane==0) wcnt[wid]=__popc(m);
    __syncthreads();
    int basec=0;
    #pragma unroll
    for(int w=0;w<4;w++) if(w<wid) basec+=wcnt[w];
    int rslot = basec + __popc(m & ((1u<<lane)-1u));
    if(i==0) d_rcnt[bn]=wcnt[0]+wcnt[1]+wcnt[2]+wcnt[3];
    if(act){
        d_rnbr[bn*NA+rslot]=i;
        d_redg[bn*NA+rslot]=(b*NA+i)*ND + s;
    }
}

// ---------------- init ----------------
__global__ void k_init(const int* __restrict__ z, const float* __restrict__ embed){
    int bn=blockIdx.x; int b=bn/NA, n=bn%NA;
    int f=threadIdx.x;
    float* x=d_x0+(size_t)bn*LF;
    x[f]=embed[z[b*NA+n]*NF+f];
    #pragma unroll
    for(int l=1;l<9;l++) x[l*NF+f]=0.f;
}

// ---------------- forward message (chunked) ----------------
__global__ void k_msg(const float* __restrict__ WA, const float* __restrict__ WB, int layer){
    int bn=blockIdx.x; int b=bn/NA;
    int t=threadIdx.x, l=t/NF, f=t%NF;
    const float* xin = layer? d_x1 : d_x0;
    __shared__ float sWA[NK*SF], sWB[NK*SF];
    __shared__ float sB[CH][NL*SK];
    __shared__ float sxs[CH][LF];
    for(int i=t;i<NK*NF;i+=LF){int k=i>>6,ff=i&63; sWA[k*SF+ff]=WA[i]; sWB[k*SF+ff]=WB[i];}
    int cnt=d_cnt[bn];
    float acc = xin[(size_t)bn*LF+t];
    int cg=t/LK, ig=t%LK, lg=ig>>4, kg=ig&15;
    for(int base=0;base<cnt;base+=CH){
        __syncthreads();
        if(base+cg<cnt)
            sB[cg][lg*SK+kg]=d_Bc[((size_t)bn*ND+base+cg)*LK+ig];
        #pragma unroll
        for(int c=0;c<CH;c++) if(base+c<cnt){
            int src=__ldg(&d_nbr[bn*NA+base+c]);
            sxs[c][t]=xin[((size_t)b*NA+src)*LF+t];
        }
        __syncthreads();
        #pragma unroll
        for(int c=0;c<CH;c++) if(base+c<cnt){
            float A=0.f,s0=0.f;
            #pragma unroll
            for(int k=0;k<NK;k++){ A=fmaf(sB[c][l*SK+k],sWA[k*SF+f],A); s0=fmaf(sB[c][k],sWB[k*SF+f],s0); }
            acc=fmaf(A,sxs[c][f],acc);
            acc=fmaf(sxs[c][t],s0,acc);
        }
    }
    d_y1buf[(size_t)bn*LF+t]=acc;
}

// ---------------- node update ----------------
__global__ void k_node(const float* __restrict__ W1, const float* __restrict__ b1,
                       const float* __restrict__ W2, int layer){
    int bn=blockIdx.x;
    int t=threadIdx.x, l=t/NF, g=t%NF;
    int deg=c_deg[l];
    const float* xin = layer? d_x1 : d_x0;
    float* xout = layer? d_x2 : d_x1;
    float* y2out= layer? d_y2b : d_y2a;
    __shared__ float sy1[LF], sy2[LF], sy3[LF];
    size_t base=(size_t)bn*LF;
    sy1[t]=d_y1buf[base+t];
    __syncthreads();
    const float* w1=W1+deg*4096;
    float v=0.f;
    for(int f=0;f<NF;f++) v=fmaf(sy1[l*NF+f],w1[f*NF+g],v);
    if(l==0) v+=b1[g];
    sy2[t]=v; y2out[base+t]=v;
    __syncthreads();
    float s=sy2[g];
    float sig=1.f/(1.f+expf(-s));
    float y3=(l==0)? s*sig : v*sig;
    sy3[t]=y3;
    __syncthreads();
    const float* w2=W2+deg*4096;
    float o=0.f;
    for(int f=0;f<NF;f++) o=fmaf(sy3[l*NF+f],w2[f*NF+g],o);
    xout[base+t]=xin[base+t]+o;
}

// ---------------- final edge forward ----------------
__global__ void k_final_edge(const float* __restrict__ WA2, const float* __restrict__ WB2){
    int bn=blockIdx.x; int b=bn/NA;
    int t=threadIdx.x, l=t/NF, f=t%NF;
    __shared__ float sWA[NK*SF], sWB[NK*SF];
    __shared__ float sB[CH][NL*SK];
    __shared__ float sxs[CH][LF];
    __shared__ float sred[LF];
    for(int i=t;i<NK*NF;i+=LF){int k=i>>6,ff=i&63; sWA[k*SF+ff]=WA2[i]; sWB[k*SF+ff]=WB2[i];}
    int cnt=d_cnt[bn];
    float acc=0.f;
    int cg=t/LK, ig=t%LK, lg=ig>>4, kg=ig&15;
    for(int base=0;base<cnt;base+=CH){
        __syncthreads();
        if(base+cg<cnt)
            sB[cg][lg*SK+kg]=d_Bc[((size_t)bn*ND+base+cg)*LK+ig];
        #pragma unroll
        for(int c=0;c<CH;c++) if(base+c<cnt){
            int src=__ldg(&d_nbr[bn*NA+base+c]);
            sxs[c][t]=d_x2[((size_t)b*NA+src)*LF+t];
        }
        __syncthreads();
        #pragma unroll
        for(int c=0;c<CH;c++) if(base+c<cnt){
            float sbw=0.f;
            #pragma unroll
            for(int k=0;k<NK;k++) sbw=fmaf(sB[c][l*SK+k],sWB[k*SF+f],sbw);
            acc=fmaf(sxs[c][t],sbw,acc);
            if(l==0){
                float a2=0.f;
                #pragma unroll
                for(int k=0;k<NK;k++) a2=fmaf(sB[c][k],sWA[k*SF+f],a2);
                acc=fmaf(a2,sxs[c][f],acc);
            }
        }
    }
    __syncthreads();
    sred[t]=acc;
    __syncthreads();
    if(l==0){
        float ss=0.f;
        #pragma unroll
        for(int l2=0;l2<NL;l2++) ss+=sred[l2*NF+f];
        d_yF[bn*NF+f]=ss;
    }
}

// ---------------- final node fwd+bwd ----------------
__global__ void k_final_node(const int* __restrict__ z,
                             const float* __restrict__ W1s, const float* __restrict__ b1s,
                             const float* __restrict__ W2s, const float* __restrict__ w_out,
                             const float* __restrict__ ebias){
    int bn=blockIdx.x; int b=bn/NA, n=bn%NA;
    int f=threadIdx.x;
    __shared__ float sh0[NF], sq[NF], sdp[NF], sred[NF];
    size_t base=(size_t)bn*LF;
    float x0=d_x2[base+f];
    float h0=x0+d_yF[bn*NF+f];
    sh0[f]=h0; __syncthreads();
    float p=b1s[f];
    for(int g=0;g<NF;g++) p=fmaf(sh0[g],W1s[g*NF+f],p);
    float sig=1.f/(1.f+expf(-p));
    float q=p*sig;
    sq[f]=q; __syncthreads();
    float hh=0.f;
    for(int g=0;g<NF;g++) hh=fmaf(sq[g],W2s[g*NF+f],hh);
    float xo=x0+hh;
    sred[f]=xo*w_out[f]; __syncthreads();
    for(int s=32;s>0;s>>=1){ if(f<s) sred[f]+=sred[f+s]; __syncthreads(); }
    if(f==0) d_ae[bn]=sred[0]+ebias[z[b*NA+n]];
    float dq=0.f;
    for(int g=0;g<NF;g++) dq=fmaf(w_out[g],W2s[f*NF+g],dq);
    float dp=dq*sig*(1.f+p*(1.f-sig));
    sdp[f]=dp; __syncthreads();
    float dh0=0.f;
    for(int g=0;g<NF;g++) dh0=fmaf(sdp[g],W1s[f*NF+g],dh0);
    d_dh0[bn*NF+f]=dh0;
    float* gx=d_gxA+base;
    gx[f]=w_out[f]+dh0;
    #pragma unroll
    for(int l=1;l<9;l++) gx[l*NF+f]=0.f;
}

__global__ void k_energy(float* __restrict__ out){
    int b=blockIdx.x;
    __shared__ float sh[NA];
    sh[threadIdx.x]=d_ae[b*NA+threadIdx.x];
    __syncthreads();
    for(int s=64;s>0;s>>=1){ if(threadIdx.x<s) sh[threadIdx.x]+=sh[threadIdx.x+s]; __syncthreads(); }
    if(threadIdx.x==0) out[b]=sh[0];
}

// ---------------- backward final edge ----------------
__global__ void kb_final_edge(const float* __restrict__ WA2, const float* __restrict__ WB2){
    int bn=blockIdx.x; int b=bn/NA;
    int t=threadIdx.x, l=t/NF, f=t%NF;
    __shared__ float sWA[NK*SF], sWB[NK*SF];
    __shared__ float sB[CH][NL*SK];
    __shared__ float sdm[CH][NF];
    __shared__ float sxj[NL*SF];
    for(int i=t;i<NK*NF;i+=LF){int k=i>>6,ff=i&63; sWA[k*SF+ff]=WA2[i]; sWB[k*SF+ff]=WB2[i];}
    sxj[l*SF+f]=d_x2[(size_t)bn*LF+t];
    int rc=d_rcnt[bn];
    float acc=0.f;
    int cg=t/LK, ig=t%LK, lg=ig>>4, kg=ig&15;
    for(int base=0;base<rc;base+=CH){
        __syncthreads();
        if(base+cg<rc){
            int e=__ldg(&d_redg[bn*NA+base+cg]);
            sB[cg][lg*SK+kg]=d_Bc[(size_t)e*LK+ig];
        }
        if(t<CH*NF){
            int c=t>>6, ff=t&63;
            if(base+c<rc){
                int idst=__ldg(&d_rnbr[bn*NA+base+c]);
                sdm[c][ff]=d_dh0[(b*NA+idst)*NF+ff];
            }
        }
        __syncthreads();
        #pragma unroll
        for(int c=0;c<CH;c++) if(base+c<rc){
            float sbw=0.f;
            #pragma unroll
            for(int k=0;k<NK;k++) sbw=fmaf(sB[c][l*SK+k],sWB[k*SF+f],sbw);
            float g=sbw;
            if(l==0){
                float a2=0.f;
                #pragma unroll
                for(int k=0;k<NK;k++) a2=fmaf(sB[c][k],sWA[k*SF+f],a2);
                g+=a2;
            }
            acc=fmaf(sdm[c][f],g,acc);
        }
        if(base+cg<rc){
            float gg=0.f;
            for(int ff=0;ff<NF;ff++) gg=fmaf(sdm[cg][ff]*sWB[kg*SF+ff],sxj[lg*SF+ff],gg);
            if(lg==0)
                for(int ff=0;ff<NF;ff++) gg=fmaf(sdm[cg][ff]*sxj[ff],sWA[kg*SF+ff],gg);
            int e=__ldg(&d_redg[bn*NA+base+cg]);
            d_gB[(size_t)e*LK+ig]=gg;
        }
    }
    d_gxA[(size_t)bn*LF+t]+=acc;
}

// ---------------- backward node ----------------
__global__ void kb_node(const float* __restrict__ W1, const float* __restrict__ W2, int layer){
    int bn=blockIdx.x;
    int t=threadIdx.x, l=t/NF, f=t%NF;
    int deg=c_deg[l];
    const float* gxin=(layer==1)? d_gxA : d_gxB;
    const float* y2  =(layer==1)? d_y2b : d_y2a;
    __shared__ float sgxo[LF], sy2[LF], sgy3[LF], sgy2[LF];
    size_t base=(size_t)bn*LF;
    sgxo[t]=gxin[base+t]; sy2[t]=y2[base+t];
    __syncthreads();
    const float* w2=W2+deg*4096+f*NF;
    float gy3=0.f;
    for(int g=0;g<NF;g++) gy3=fmaf(sgxo[l*NF+g],w2[g],gy3);
    sgy3[t]=gy3;
    __syncthreads();
    float s=sy2[f];
    float sig=1.f/(1.f+expf(-s));
    float gy2;
    if(l==0){
        float a=0.f;
        #pragma unroll
        for(int l2=1;l2<NL;l2++) a=fmaf(sgy3[l2*NF+f],sy2[l2*NF+f],a);
        gy2=gy3*sig*(1.f+s*(1.f-sig))+a*sig*(1.f-sig);
    } else gy2=gy3*sig;
    sgy2[t]=gy2;
    __syncthreads();
    const float* w1=W1+deg*4096+f*NF;
    float gy1=0.f;
    for(int g=0;g<NF;g++) gy1=fmaf(sgy2[l*NF+g],w1[g],gy1);
    d_gy1[base+t]=gy1;
    if(layer==1) d_gxB[base+t]=sgxo[t]+gy1;
}

// ---------------- backward layer edge ----------------
__global__ void kb_edge(const float* __restrict__ WA, const float* __restrict__ WB, int layer){
    int bn=blockIdx.x; int b=bn/NA;
    int t=threadIdx.x, l=t/NF, f=t%NF;
    const float* xin = layer? d_x1 : d_x0;
    __shared__ float sWA[NK*SF], sWB[NK*SF];
    __shared__ float sB[CH][NL*SK];
    __shared__ float sgm[CH][NL*SF];
    __shared__ float sxj[NL*SF];
    __shared__ float sgs0[CH][NF];
    for(int i=t;i<NK*NF;i+=LF){int k=i>>6,ff=i&63; sWA[k*SF+ff]=WA[i]; sWB[k*SF+ff]=WB[i];}
    sxj[l*SF+f]=xin[(size_t)bn*LF+t];
    int rc=d_rcnt[bn];
    float acc=0.f;
    int cg=t/LK, ig=t%LK, lg=ig>>4, kg=ig&15;
    for(int base=0;base<rc;base+=CH){
        __syncthreads();
        if(base+cg<rc){
            int e=__ldg(&d_redg[bn*NA+base+cg]);
            sB[cg][lg*SK+kg]=d_Bc[(size_t)e*LK+ig];
        }
        #pragma unroll
        for(int c=0;c<CH;c++) if(base+c<rc){
            int idst=__ldg(&d_rnbr[bn*NA+base+c]);
            sgm[c][l*SF+f]=d_gy1[((size_t)b*NA+idst)*LF+t];
        }
        __syncthreads();
        #pragma unroll
        for(int c=0;c<CH;c++) if(base+c<rc){
            float s0=0.f;
            #pragma unroll
            for(int k=0;k<NK;k++) s0=fmaf(sB[c][k],sWB[k*SF+f],s0);
            acc=fmaf(sgm[c][l*SF+f],s0,acc);
            if(l==0){
                float sa=0.f, ss=0.f;
                #pragma unroll
                for(int l2=0;l2<NL;l2++){
                    float A=0.f;
                    #pragma unroll
                    for(int k=0;k<NK;k++) A=fmaf(sB[c][l2*SK+k],sWA[k*SF+f],A);
                    sa=fmaf(sgm[c][l2*SF+f],A,sa);
                    ss=fmaf(sgm[c][l2*SF+f],sxj[l2*SF+f],ss);
                }
                acc+=sa;
                sgs0[c][f]=ss;
            }
        }
        __syncthreads();
        if(base+cg<rc){
            float gg=0.f;
            for(int ff=0;ff<NF;ff++) gg=fmaf(sgm[cg][lg*SF+ff]*sxj[ff],sWA[kg*SF+ff],gg);
            if(lg==0)
                for(int ff=0;ff<NF;ff++) gg=fmaf(sgs0[cg][ff],sWB[kg*SF+ff],gg);
            int e=__ldg(&d_redg[bn*NA+base+cg]);
            d_gB[(size_t)e*LK+ig]+=gg;
        }
    }
    if(layer==1) d_gxB[(size_t)bn*LF+t]+=acc;
}

// ---------------- basis geometry backward ----------------
__global__ void k_ddisp(const float* __restrict__ pos){
    int bn=blockIdx.x; int b=bn/NA, dst=bn%NA;
    int s=threadIdx.x;
    if(s>=d_cnt[bn]) return;
    int src=d_nbr[bn*NA+s];
    const float* pd=pos+(b*NA+dst)*3;
    const float* ps=pos+(b*NA+src)*3;
    float dx=ps[0]-pd[0], dy=ps[1]-pd[1], dz=ps[2]-pd[2];
    float r2=dx*dx+dy*dy+dz*dz+1e-12f;
    float r=sqrtf(r2), inv_r=1.f/r;
    float ux=dx*inv_r, uy=dy*inv_r, uz=dz*inv_r;
    float om=1.f-r2/CUT2;
    float cut=expf(1.f-1.f/om);
    float dcut=cut*(-2.f*r/CUT2)/(om*om);
    float w=1.f/(1.f+r), v=1.f-w, dwdr=-w*w;
    float wp[16], vp[16];
    wp[0]=1.f; vp[0]=1.f;
    #pragma unroll
    for(int q=1;q<16;q++){ wp[q]=wp[q-1]*w; vp[q]=vp[q-1]*v; }
    float Y[9];
    Y[0]=1.f; Y[1]=ux; Y[2]=uy; Y[3]=uz;
    Y[4]=SQ3f*ux*uy; Y[5]=SQ3f*uy*uz; Y[6]=0.5f*(3.f*uz*uz-1.f);
    Y[7]=SQ3f*ux*uz; Y[8]=0.5f*SQ3f*(ux*ux-uy*uy);
    float rad[16], drd[16];
    #pragma unroll
    for(int k=0;k<16;k++){
        rad[k]=c_binom[k]*wp[k]*vp[15-k];
        float t1=(k>0)  ? k*wp[k-1]*vp[15-k]    : 0.f;
        float t2=(k<15) ? (15-k)*wp[k]*vp[14-k] : 0.f;
        drd[k]=c_binom[k]*(t1-t2)*dwdr;
    }
    const float* g=d_gB+((size_t)bn*ND+s)*LK;
    float gY[9];
    #pragma unroll
    for(int l=0;l<9;l++){
        float sacc=0.f;
        #pragma unroll
        for(int k=0;k<16;k++) sacc=fmaf(g[l*16+k],rad[k],sacc);
        gY[l]=sacc*cut;
    }
    float gr=0.f;
    #pragma unroll
    for(int k=0;k<16;k++){
        float sacc=0.f;
        #pragma unroll
        for(int l=0;l<9;l++) sacc=fmaf(g[l*16+k],Y[l],sacc);
        gr=fmaf(sacc,drd[k]*cut+rad[k]*dcut,gr);
    }
    float gux=gY[1]+SQ3f*(gY[4]*uy+gY[7]*uz+gY[8]*ux);
    float guy=gY[2]+SQ3f*(gY[4]*ux+gY[5]*uz-gY[8]*uy);
    float guz=gY[3]+SQ3f*(gY[5]*uy+gY[7]*ux)+3.f*gY[6]*uz;
    float gd=gux*ux+guy*uy+guz*uz;
    float* dd=d_dd+((size_t)bn*ND+s)*3;
    dd[0]=(gux-gd*ux)*inv_r+gr*ux;
    dd[1]=(guy-gd*uy)*inv_r+gr*uy;
    dd[2]=(guz-gd*uz)*inv_r+gr*uz;
}

// ---------------- forces ----------------
__global__ void k_force(float* __restrict__ out){
    int bn=blockIdx.x;
    int s=threadIdx.x;
    float fx=0.f,fy=0.f,fz=0.f;
    int cnt=d_cnt[bn], rc=d_rcnt[bn];
    if(s<cnt){
        const float* dd=d_dd+((size_t)bn*ND+s)*3;
        fx+=dd[0]; fy+=dd[1]; fz+=dd[2];
    }
    if(s<rc){
        int e=d_redg[bn*NA+s];
        const float* dd=d_dd+(size_t)e*3;
        fx-=dd[0]; fy-=dd[1]; fz-=dd[2];
    }
    __shared__ float rx[128],ry[128],rz[128];
    rx[s]=fx; ry[s]=fy; rz[s]=fz;
    __syncthreads();
    for(int st=64;st>0;st>>=1){
        if(s<st){ rx[s]+=rx[s+st]; ry[s]+=ry[s+st]; rz[s]+=rz[s+st]; }
        __syncthreads();
    }
    if(s==0){
        float* F=out+NB+(size_t)bn*3;
        F[0]=rx[0]; F[1]=ry[0]; F[2]=rz[0];
    }
}

// ---------------- launch ----------------
extern "C" void kernel_launch(void* const* d_in, const int* in_sizes, int n_in,
                              void* d_out, int out_size){
    const int*   z     = (const int*)  d_in[0];
    const float* pos   = (const float*)d_in[1];
    const float* embed = (const float*)d_in[2];
    const float* WA    = (const float*)d_in[3];
    const float* WB    = (const float*)d_in[4];
    const float* W1    = (const float*)d_in[5];
    const float* b1    = (const float*)d_in[6];
    const float* W2    = (const float*)d_in[7];
    const float* W1s   = (const float*)d_in[8];
    const float* b1s   = (const float*)d_in[9];
    const float* W2s   = (const float*)d_in[10];
    const float* w_out = (const float*)d_in[11];
    const float* ebias = (const float*)d_in[12];
    float* out = (float*)d_out;

    k_geom<<<NB*NA,128>>>(pos);
    k_rev <<<NB*NA,128>>>();
    k_init<<<NB*NA,NF>>>(z, embed);

    k_msg  <<<NB*NA,LF>>>(WA+0*NK*NF, WB+0*NK*NF, 0);
    k_node <<<NB*NA,LF>>>(W1+0*3*4096, b1+0*NF, W2+0*3*4096, 0);
    k_msg  <<<NB*NA,LF>>>(WA+1*NK*NF, WB+1*NK*NF, 1);
    k_node <<<NB*NA,LF>>>(W1+1*3*4096, b1+1*NF, W2+1*3*4096, 1);

    k_final_edge<<<NB*NA,LF>>>(WA+2*NK*NF, WB+2*NK*NF);
    k_final_node<<<NB*NA,NF>>>(z, W1s, b1s, W2s, w_out, ebias);
    k_energy    <<<NB,NA>>>(out);

    kb_final_edge<<<NB*NA,LF>>>(WA+2*NK*NF, WB+2*NK*NF);

    kb_node<<<NB*NA,LF>>>(W1+1*3*4096, W2+1*3*4096, 1);
    kb_edge<<<NB*NA,LF>>>(WA+1*NK*NF, WB+1*NK*NF, 1);
    kb_node<<<NB*NA,LF>>>(W1+0*3*4096, W2+0*3*4096, 0);
    kb_edge<<<NB*NA,LF>>>(WA+0*NK*NF, WB+0*NK*NF, 0);

    k_ddisp<<<NB*NA,128>>>(pos);
    k_force<<<NB*NA,128>>>(out);
}

// round 5
// speedup vs baseline: 1.7333x; 1.1129x over previous
#include <cuda_runtime.h>
#include <math.h>

#define NB 8
#define NA 128
#define ND 127
#define NL 9
#define NF 64
#define NK 16
#define LF (NL*NF)       // 576
#define LK (NL*NK)       // 144
#define GS 68            // padded row stride for float4 dot loops (68*4B=272B, 16B-aligned)
#define SQ3f 1.7320508075688772f
#define CUT2 25.0f
#define CH 4             // edge chunk

// ---------------- scratch ----------------
__device__ float d_Bc[(size_t)NB*NA*ND*LK];
__device__ float d_gB[(size_t)NB*NA*ND*LK];
__device__ float d_dd[(size_t)NB*NA*ND*3];
__device__ int   d_cnt [NB*NA];
__device__ int   d_rcnt[NB*NA];
__device__ int   d_nbr [NB*NA*NA];
__device__ int   d_slot[NB*NA*NA];
__device__ int   d_rnbr[NB*NA*NA];
__device__ int   d_redg[NB*NA*NA];
__device__ float d_x0[(size_t)NB*NA*LF];
__device__ float d_x1[(size_t)NB*NA*LF];
__device__ float d_x2[(size_t)NB*NA*LF];
__device__ float d_y1buf[(size_t)NB*NA*LF];
__device__ float d_y2a[(size_t)NB*NA*LF];
__device__ float d_y2b[(size_t)NB*NA*LF];
__device__ float d_yF[NB*NA*NF];
__device__ float d_dh0[NB*NA*NF];
__device__ float d_gxA[(size_t)NB*NA*LF];
__device__ float d_gxB[(size_t)NB*NA*LF];
__device__ float d_gy1[(size_t)NB*NA*LF];
__device__ float d_ae[NB*NA];

__constant__ int   c_deg[9]    = {0,1,1,1,2,2,2,2,2};
__constant__ float c_binom[16] = {1.f,15.f,105.f,455.f,1365.f,3003.f,5005.f,6435.f,
                                  6435.f,5005.f,3003.f,1365.f,455.f,105.f,15.f,1.f};

__device__ __forceinline__ float dot4(float4 a, const float* w){
    return fmaf(a.x,w[0],fmaf(a.y,w[1],fmaf(a.z,w[2],a.w*w[3])));
}

// ---------------- geometry + compaction + basis ----------------
__global__ void k_geom(const float* __restrict__ pos){
    int bn = blockIdx.x; int b=bn/NA, dst=bn%NA;
    int j = threadIdx.x;
    float pdx=pos[(b*NA+dst)*3+0], pdy=pos[(b*NA+dst)*3+1], pdz=pos[(b*NA+dst)*3+2];
    float dx=0.f,dy=0.f,dz=0.f,r2=1.f; bool act=false;
    if(j!=dst){
        dx=pos[(b*NA+j)*3+0]-pdx;
        dy=pos[(b*NA+j)*3+1]-pdy;
        dz=pos[(b*NA+j)*3+2]-pdz;
        r2=dx*dx+dy*dy+dz*dz+1e-12f;
        act = (1.f - r2/CUT2) > 1e-6f;
    }
    unsigned m=__ballot_sync(0xffffffffu, act);
    int wid=j>>5, lane=j&31;
    __shared__ int wcnt[4];
    if(lane==0) wcnt[wid]=__popc(m);
    __syncthreads();
    int basec=0;
    #pragma unroll
    for(int w=0;w<4;w++) if(w<wid) basec+=wcnt[w];
    int slot = basec + __popc(m & ((1u<<lane)-1u));
    if(j==0) d_cnt[bn]=wcnt[0]+wcnt[1]+wcnt[2]+wcnt[3];
    d_slot[bn*NA+j] = act ? slot : -1;
    if(!act) return;
    d_nbr[bn*NA+slot]=j;
    float om = 1.f - r2/CUT2;
    float r=sqrtf(r2), inv=1.f/r;
    float ux=dx*inv, uy=dy*inv, uz=dz*inv;
    float Y[9];
    Y[0]=1.f; Y[1]=ux; Y[2]=uy; Y[3]=uz;
    Y[4]=SQ3f*ux*uy; Y[5]=SQ3f*uy*uz; Y[6]=0.5f*(3.f*uz*uz-1.f);
    Y[7]=SQ3f*ux*uz; Y[8]=0.5f*SQ3f*(ux*ux-uy*uy);
    float w=1.f/(1.f+r), v=1.f-w;
    float cut=expf(1.f-1.f/om);
    float vp[16]; vp[0]=1.f;
    #pragma unroll
    for(int q=1;q<16;q++) vp[q]=vp[q-1]*v;
    float rad[16]; float wk=1.f;
    #pragma unroll
    for(int k=0;k<16;k++){ rad[k]=c_binom[k]*wk*vp[15-k]; wk*=w; }
    float4* Bo=(float4*)(d_Bc+((size_t)bn*ND+slot)*LK);
    #pragma unroll
    for(int l=0;l<9;l++){
        float yc=Y[l]*cut;
        #pragma unroll
        for(int q=0;q<4;q++)
            Bo[l*4+q]=make_float4(yc*rad[4*q],yc*rad[4*q+1],yc*rad[4*q+2],yc*rad[4*q+3]);
    }
}

__global__ void k_rev(){
    int bn=blockIdx.x; int b=bn/NA, j=bn%NA;
    int i=threadIdx.x;
    int s = (i!=j) ? d_slot[(b*NA+i)*NA + j] : -1;
    bool act = s>=0;
    unsigned m=__ballot_sync(0xffffffffu, act);
    int wid=i>>5, lane=i&31;
    __shared__ int wcnt[4];
    if(lane==0) wcnt[wid]=__popc(m);
    __syncthreads();
    int basec=0;
    #pragma unroll
    for(int w=0;w<4;w++) if(w<wid) basec+=wcnt[w];
    int rslot = basec + __popc(m & ((1u<<lane)-1u));
    if(i==0) d_rcnt[bn]=wcnt[0]+wcnt[1]+wcnt[2]+wcnt[3];
    if(act){
        d_rnbr[bn*NA+rslot]=i;
        d_redg[bn*NA+rslot]=(b*NA+i)*ND + s;
    }
}

// ---------------- init ----------------
__global__ void k_init(const int* __restrict__ z, const float* __restrict__ embed){
    int bn=blockIdx.x; int b=bn/NA, n=bn%NA;
    int f=threadIdx.x;
    float* x=d_x0+(size_t)bn*LF;
    x[f]=embed[z[b*NA+n]*NF+f];
    #pragma unroll
    for(int l=1;l<9;l++) x[l*NF+f]=0.f;
}

// ---------------- forward message ----------------
__global__ void __launch_bounds__(LF,1) k_msg(const float* __restrict__ WA, const float* __restrict__ WB, int layer){
    int bn=blockIdx.x; int b=bn/NA;
    int t=threadIdx.x, l=t/NF, f=t%NF;
    const float* xin = layer? d_x1 : d_x0;
    __shared__ __align__(16) float sB[CH][LK];
    __shared__ float sxs[CH][LF];
    float rWA[16], rWB[16];
    #pragma unroll
    for(int k=0;k<16;k++){ rWA[k]=WA[k*NF+f]; rWB[k]=WB[k*NF+f]; }
    int cnt=d_cnt[bn];
    float acc = xin[(size_t)bn*LF+t];
    int cg=t/LK, ig=t%LK;
    for(int base=0;base<cnt;base+=CH){
        __syncthreads();
        if(base+cg<cnt) sB[cg][ig]=d_Bc[((size_t)bn*ND+base+cg)*LK+ig];
        #pragma unroll
        for(int c=0;c<CH;c++) if(base+c<cnt){
            int src=__ldg(&d_nbr[bn*NA+base+c]);
            sxs[c][t]=xin[((size_t)b*NA+src)*LF+t];
        }
        __syncthreads();
        #pragma unroll
        for(int c=0;c<CH;c++) if(base+c<cnt){
            const float4* B4l=(const float4*)(sB[c]+l*16);
            const float4* B40=(const float4*)(sB[c]);
            float A=0.f,s0=0.f;
            #pragma unroll
            for(int q=0;q<4;q++){
                A  += dot4(B4l[q], rWA+4*q);
                s0 += dot4(B40[q], rWB+4*q);
            }
            acc=fmaf(A,sxs[c][f],acc);
            acc=fmaf(sxs[c][t],s0,acc);
        }
    }
    d_y1buf[(size_t)bn*LF+t]=acc;
}

// ---------------- node update ----------------
__global__ void __launch_bounds__(LF,1) k_node(const float* __restrict__ W1, const float* __restrict__ b1,
                       const float* __restrict__ W2, int layer){
    int bn=blockIdx.x;
    int t=threadIdx.x, l=t/NF, g=t%NF;
    int deg=c_deg[l];
    const float* xin = layer? d_x1 : d_x0;
    float* xout = layer? d_x2 : d_x1;
    float* y2out= layer? d_y2b : d_y2a;
    __shared__ float sy1[LF], sy2[LF], sy3[LF];
    size_t base=(size_t)bn*LF;
    sy1[t]=d_y1buf[base+t];
    __syncthreads();
    const float* w1=W1+deg*4096;
    float v=0.f;
    for(int f=0;f<NF;f++) v=fmaf(sy1[l*NF+f],w1[f*NF+g],v);
    if(l==0) v+=b1[g];
    sy2[t]=v; y2out[base+t]=v;
    __syncthreads();
    float s=sy2[g];
    float sig=1.f/(1.f+expf(-s));
    float y3=(l==0)? s*sig : v*sig;
    sy3[t]=y3;
    __syncthreads();
    const float* w2=W2+deg*4096;
    float o=0.f;
    for(int f=0;f<NF;f++) o=fmaf(sy3[l*NF+f],w2[f*NF+g],o);
    xout[base+t]=xin[base+t]+o;
}

// ---------------- final edge forward ----------------
__global__ void __launch_bounds__(LF,1) k_final_edge(const float* __restrict__ WA2, const float* __restrict__ WB2){
    int bn=blockIdx.x; int b=bn/NA;
    int t=threadIdx.x, l=t/NF, f=t%NF;
    __shared__ __align__(16) float sB[CH][LK];
    __shared__ float sxs[CH][LF];
    __shared__ float sred[LF];
    float rWA[16], rWB[16];
    #pragma unroll
    for(int k=0;k<16;k++){ rWA[k]=WA2[k*NF+f]; rWB[k]=WB2[k*NF+f]; }
    int cnt=d_cnt[bn];
    float acc=0.f;
    int cg=t/LK, ig=t%LK;
    for(int base=0;base<cnt;base+=CH){
        __syncthreads();
        if(base+cg<cnt) sB[cg][ig]=d_Bc[((size_t)bn*ND+base+cg)*LK+ig];
        #pragma unroll
        for(int c=0;c<CH;c++) if(base+c<cnt){
            int src=__ldg(&d_nbr[bn*NA+base+c]);
            sxs[c][t]=d_x2[((size_t)b*NA+src)*LF+t];
        }
        __syncthreads();
        #pragma unroll
        for(int c=0;c<CH;c++) if(base+c<cnt){
            const float4* B4l=(const float4*)(sB[c]+l*16);
            float sbw=0.f;
            #pragma unroll
            for(int q=0;q<4;q++) sbw += dot4(B4l[q], rWB+4*q);
            acc=fmaf(sxs[c][t],sbw,acc);
            if(l==0){
                const float4* B40=(const float4*)(sB[c]);
                float a2=0.f;
                #pragma unroll
                for(int q=0;q<4;q++) a2 += dot4(B40[q], rWA+4*q);
                acc=fmaf(a2,sxs[c][f],acc);
            }
        }
    }
    __syncthreads();
    sred[t]=acc;
    __syncthreads();
    if(l==0){
        float ss=0.f;
        #pragma unroll
        for(int l2=0;l2<NL;l2++) ss+=sred[l2*NF+f];
        d_yF[bn*NF+f]=ss;
    }
}

// ---------------- final node fwd+bwd ----------------
__global__ void k_final_node(const int* __restrict__ z,
                             const float* __restrict__ W1s, const float* __restrict__ b1s,
                             const float* __restrict__ W2s, const float* __restrict__ w_out,
                             const float* __restrict__ ebias){
    int bn=blockIdx.x; int b=bn/NA, n=bn%NA;
    int f=threadIdx.x;
    __shared__ float sh0[NF], sq[NF], sdp[NF], sred[NF];
    size_t base=(size_t)bn*LF;
    float x0=d_x2[base+f];
    float h0=x0+d_yF[bn*NF+f];
    sh0[f]=h0; __syncthreads();
    float p=b1s[f];
    for(int g=0;g<NF;g++) p=fmaf(sh0[g],W1s[g*NF+f],p);
    float sig=1.f/(1.f+expf(-p));
    float q=p*sig;
    sq[f]=q; __syncthreads();
    float hh=0.f;
    for(int g=0;g<NF;g++) hh=fmaf(sq[g],W2s[g*NF+f],hh);
    float xo=x0+hh;
    sred[f]=xo*w_out[f]; __syncthreads();
    for(int s=32;s>0;s>>=1){ if(f<s) sred[f]+=sred[f+s]; __syncthreads(); }
    if(f==0) d_ae[bn]=sred[0]+ebias[z[b*NA+n]];
    float dq=0.f;
    for(int g=0;g<NF;g++) dq=fmaf(w_out[g],W2s[f*NF+g],dq);
    float dp=dq*sig*(1.f+p*(1.f-sig));
    sdp[f]=dp; __syncthreads();
    float dh0=0.f;
    for(int g=0;g<NF;g++) dh0=fmaf(sdp[g],W1s[f*NF+g],dh0);
    d_dh0[bn*NF+f]=dh0;
    float* gx=d_gxA+base;
    gx[f]=w_out[f]+dh0;
    #pragma unroll
    for(int l=1;l<9;l++) gx[l*NF+f]=0.f;
}

__global__ void k_energy(float* __restrict__ out){
    int b=blockIdx.x;
    __shared__ float sh[NA];
    sh[threadIdx.x]=d_ae[b*NA+threadIdx.x];
    __syncthreads();
    for(int s=64;s>0;s>>=1){ if(threadIdx.x<s) sh[threadIdx.x]+=sh[threadIdx.x+s]; __syncthreads(); }
    if(threadIdx.x==0) out[b]=sh[0];
}

// ---------------- backward final edge ----------------
__global__ void __launch_bounds__(LF,1) kb_final_edge(const float* __restrict__ WA2, const float* __restrict__ WB2){
    int bn=blockIdx.x; int b=bn/NA;
    int t=threadIdx.x, l=t/NF, f=t%NF;
    __shared__ __align__(16) float sWAp[NK*GS], sWBp[NK*GS];
    __shared__ __align__(16) float sB[CH][LK];
    __shared__ __align__(16) float sdm[CH][NF];
    __shared__ __align__(16) float sxj[NL*GS];
    float rWA[16], rWB[16];
    #pragma unroll
    for(int k=0;k<16;k++){ rWA[k]=WA2[k*NF+f]; rWB[k]=WB2[k*NF+f]; }
    for(int i=t;i<NK*NF;i+=LF){int k=i>>6,ff=i&63; sWAp[k*GS+ff]=WA2[i]; sWBp[k*GS+ff]=WB2[i];}
    sxj[l*GS+f]=d_x2[(size_t)bn*LF+t];
    int rc=d_rcnt[bn];
    float acc=0.f;
    int cg=t/LK, ig=t%LK, lg=ig>>4, kg=ig&15;
    for(int base=0;base<rc;base+=CH){
        __syncthreads();
        if(base+cg<rc){
            int e=__ldg(&d_redg[bn*NA+base+cg]);
            sB[cg][ig]=d_Bc[(size_t)e*LK+ig];
        }
        if(t<CH*NF){
            int c=t>>6, ff=t&63;
            if(base+c<rc){
                int idst=__ldg(&d_rnbr[bn*NA+base+c]);
                sdm[c][ff]=d_dh0[(b*NA+idst)*NF+ff];
            }
        }
        __syncthreads();
        #pragma unroll
        for(int c=0;c<CH;c++) if(base+c<rc){
            const float4* B4l=(const float4*)(sB[c]+l*16);
            float g=0.f;
            #pragma unroll
            for(int q=0;q<4;q++) g += dot4(B4l[q], rWB+4*q);
            if(l==0){
                const float4* B40=(const float4*)(sB[c]);
                #pragma unroll
                for(int q=0;q<4;q++) g += dot4(B40[q], rWA+4*q);
            }
            acc=fmaf(sdm[c][f],g,acc);
        }
        if(base+cg<rc){
            const float4* dm4=(const float4*)(sdm[cg]);
            const float4* xj4=(const float4*)(sxj+lg*GS);
            const float4* wb4=(const float4*)(sWBp+kg*GS);
            float gg=0.f;
            #pragma unroll
            for(int q=0;q<16;q++){
                float4 d4=dm4[q], x4=xj4[q], w4=wb4[q];
                gg=fmaf(d4.x*w4.x,x4.x,gg); gg=fmaf(d4.y*w4.y,x4.y,gg);
                gg=fmaf(d4.z*w4.z,x4.z,gg); gg=fmaf(d4.w*w4.w,x4.w,gg);
            }
            if(lg==0){
                const float4* x04=(const float4*)(sxj);
                const float4* wa4=(const float4*)(sWAp+kg*GS);
                #pragma unroll
                for(int q=0;q<16;q++){
                    float4 d4=dm4[q], x4=x04[q], w4=wa4[q];
                    gg=fmaf(d4.x*x4.x,w4.x,gg); gg=fmaf(d4.y*x4.y,w4.y,gg);
                    gg=fmaf(d4.z*x4.z,w4.z,gg); gg=fmaf(d4.w*x4.w,w4.w,gg);
                }
            }
            int e=__ldg(&d_redg[bn*NA+base+cg]);
            d_gB[(size_t)e*LK+ig]=gg;
        }
    }
    d_gxA[(size_t)bn*LF+t]+=acc;
}

// ---------------- backward node ----------------
__global__ void __launch_bounds__(LF,1) kb_node(const float* __restrict__ W1, const float* __restrict__ W2, int layer){
    int bn=blockIdx.x;
    int t=threadIdx.x, l=t/NF, f=t%NF;
    int deg=c_deg[l];
    const float* gxin=(layer==1)? d_gxA : d_gxB;
    const float* y2  =(layer==1)? d_y2b : d_y2a;
    __shared__ float sgxo[LF], sy2[LF], sgy3[LF], sgy2[LF];
    size_t base=(size_t)bn*LF;
    sgxo[t]=gxin[base+t]; sy2[t]=y2[base+t];
    __syncthreads();
    const float* w2=W2+deg*4096+f*NF;
    float gy3=0.f;
    for(int g=0;g<NF;g++) gy3=fmaf(sgxo[l*NF+g],w2[g],gy3);
    sgy3[t]=gy3;
    __syncthreads();
    float s=sy2[f];
    float sig=1.f/(1.f+expf(-s));
    float gy2;
    if(l==0){
        float a=0.f;
        #pragma unroll
        for(int l2=1;l2<NL;l2++) a=fmaf(sgy3[l2*NF+f],sy2[l2*NF+f],a);
        gy2=gy3*sig*(1.f+s*(1.f-sig))+a*sig*(1.f-sig);
    } else gy2=gy3*sig;
    sgy2[t]=gy2;
    __syncthreads();
    const float* w1=W1+deg*4096+f*NF;
    float gy1=0.f;
    for(int g=0;g<NF;g++) gy1=fmaf(sgy2[l*NF+g],w1[g],gy1);
    d_gy1[base+t]=gy1;
    if(layer==1) d_gxB[base+t]=sgxo[t]+gy1;
}

// ---------------- backward layer edge ----------------
__global__ void __launch_bounds__(LF,1) kb_edge(const float* __restrict__ WA, const float* __restrict__ WB, int layer){
    int bn=blockIdx.x; int b=bn/NA;
    int t=threadIdx.x, l=t/NF, f=t%NF;
    const float* xin = layer? d_x1 : d_x0;
    __shared__ __align__(16) float sWAp[NK*GS], sWBp[NK*GS];
    __shared__ __align__(16) float sB[CH][LK];
    __shared__ __align__(16) float sgm[CH][NL*GS];
    __shared__ __align__(16) float sxj0[NF];
    __shared__ __align__(16) float sgs0[CH][NF];
    __shared__ float pA[CH][LF], pS[CH][LF];
    float rWA[16], rWB[16];
    #pragma unroll
    for(int k=0;k<16;k++){ rWA[k]=WA[k*NF+f]; rWB[k]=WB[k*NF+f]; }
    for(int i=t;i<NK*NF;i+=LF){int k=i>>6,ff=i&63; sWAp[k*GS+ff]=WA[i]; sWBp[k*GS+ff]=WB[i];}
    float xj = xin[(size_t)bn*LF+t];
    if(l==0) sxj0[f]=xj;
    int rc=d_rcnt[bn];
    float acc=0.f;
    int cg=t/LK, ig=t%LK, lg=ig>>4, kg=ig&15;
    for(int base=0;base<rc;base+=CH){
        __syncthreads();
        if(base+cg<rc){
            int e=__ldg(&d_redg[bn*NA+base+cg]);
            sB[cg][ig]=d_Bc[(size_t)e*LK+ig];
        }
        #pragma unroll
        for(int c=0;c<CH;c++) if(base+c<rc){
            int idst=__ldg(&d_rnbr[bn*NA+base+c]);
            sgm[c][l*GS+f]=d_gy1[((size_t)b*NA+idst)*LF+t];
        }
        __syncthreads();
        // phase 1: per-thread partials (balanced across all l)
        #pragma unroll
        for(int c=0;c<CH;c++) if(base+c<rc){
            float gm=sgm[c][l*GS+f];
            const float4* B4l=(const float4*)(sB[c]+l*16);
            const float4* B40=(const float4*)(sB[c]);
            float A=0.f,s0=0.f;
            #pragma unroll
            for(int q=0;q<4;q++){
                A  += dot4(B4l[q], rWA+4*q);
                s0 += dot4(B40[q], rWB+4*q);
            }
            acc=fmaf(gm,s0,acc);
            pA[c][t]=gm*A;
            pS[c][t]=gm*xj;
        }
        __syncthreads();
        // phase 2: l==0 threads fold the 9-way sums
        if(l==0){
            #pragma unroll
            for(int c=0;c<CH;c++) if(base+c<rc){
                float sa=0.f, ss=0.f;
                #pragma unroll
                for(int l2=0;l2<NL;l2++){ sa+=pA[c][l2*NF+f]; ss+=pS[c][l2*NF+f]; }
                acc+=sa;
                sgs0[c][f]=ss;
            }
        }
        __syncthreads();
        // phase 3: gB accumulation (float4 dot over f)
        if(base+cg<rc){
            const float4* gm4=(const float4*)(sgm[cg]+lg*GS);
            const float4* x04=(const float4*)(sxj0);
            const float4* wa4=(const float4*)(sWAp+kg*GS);
            float gg=0.f;
            #pragma unroll
            for(int q=0;q<16;q++){
                float4 g4=gm4[q], x4=x04[q], w4=wa4[q];
                gg=fmaf(g4.x*x4.x,w4.x,gg); gg=fmaf(g4.y*x4.y,w4.y,gg);
                gg=fmaf(g4.z*x4.z,w4.z,gg); gg=fmaf(g4.w*x4.w,w4.w,gg);
            }
            if(lg==0){
                const float4* gs4=(const float4*)(sgs0[cg]);
                const float4* wb4=(const float4*)(sWBp+kg*GS);
                #pragma unroll
                for(int q=0;q<16;q++){
                    float4 g4=gs4[q], w4=wb4[q];
                    gg=fmaf(g4.x,w4.x,gg); gg=fmaf(g4.y,w4.y,gg);
                    gg=fmaf(g4.z,w4.z,gg); gg=fmaf(g4.w,w4.w,gg);
                }
            }
            int e=__ldg(&d_redg[bn*NA+base+cg]);
            d_gB[(size_t)e*LK+ig]+=gg;
        }
    }
    if(layer==1) d_gxB[(size_t)bn*LF+t]+=acc;
}

// ---------------- basis geometry backward ----------------
__global__ void k_ddisp(const float* __restrict__ pos){
    int bn=blockIdx.x; int b=bn/NA, dst=bn%NA;
    int s=threadIdx.x;
    if(s>=d_cnt[bn]) return;
    int src=d_nbr[bn*NA+s];
    const float* pd=pos+(b*NA+dst)*3;
    const float* ps=pos+(b*NA+src)*3;
    float dx=ps[0]-pd[0], dy=ps[1]-pd[1], dz=ps[2]-pd[2];
    float r2=dx*dx+dy*dy+dz*dz+1e-12f;
    float r=sqrtf(r2), inv_r=1.f/r;
    float ux=dx*inv_r, uy=dy*inv_r, uz=dz*inv_r;
    float om=1.f-r2/CUT2;
    float cut=expf(1.f-1.f/om);
    float dcut=cut*(-2.f*r/CUT2)/(om*om);
    float w=1.f/(1.f+r), v=1.f-w, dwdr=-w*w;
    float wp[16], vp[16];
    wp[0]=1.f; vp[0]=1.f;
    #pragma unroll
    for(int q=1;q<16;q++){ wp[q]=wp[q-1]*w; vp[q]=vp[q-1]*v; }
    float Y[9];
    Y[0]=1.f; Y[1]=ux; Y[2]=uy; Y[3]=uz;
    Y[4]=SQ3f*ux*uy; Y[5]=SQ3f*uy*uz; Y[6]=0.5f*(3.f*uz*uz-1.f);
    Y[7]=SQ3f*ux*uz; Y[8]=0.5f*SQ3f*(ux*ux-uy*uy);
    float rad[16], drd[16];
    #pragma unroll
    for(int k=0;k<16;k++){
        rad[k]=c_binom[k]*wp[k]*vp[15-k];
        float t1=(k>0)  ? k*wp[k-1]*vp[15-k]    : 0.f;
        float t2=(k<15) ? (15-k)*wp[k]*vp[14-k] : 0.f;
        drd[k]=c_binom[k]*(t1-t2)*dwdr;
    }
    float g[LK];
    const float4* g4=(const float4*)(d_gB+((size_t)bn*ND+s)*LK);
    #pragma unroll
    for(int q=0;q<36;q++) ((float4*)g)[q]=g4[q];
    float gY[9];
    #pragma unroll
    for(int l=0;l<9;l++){
        float sacc=0.f;
        #pragma unroll
        for(int k=0;k<16;k++) sacc=fmaf(g[l*16+k],rad[k],sacc);
        gY[l]=sacc*cut;
    }
    float gr=0.f;
    #pragma unroll
    for(int k=0;k<16;k++){
        float sacc=0.f;
        #pragma unroll
        for(int l=0;l<9;l++) sacc=fmaf(g[l*16+k],Y[l],sacc);
        gr=fmaf(sacc,drd[k]*cut+rad[k]*dcut,gr);
    }
    float gux=gY[1]+SQ3f*(gY[4]*uy+gY[7]*uz+gY[8]*ux);
    float guy=gY[2]+SQ3f*(gY[4]*ux+gY[5]*uz-gY[8]*uy);
    float guz=gY[3]+SQ3f*(gY[5]*uy+gY[7]*ux)+3.f*gY[6]*uz;
    float gd=gux*ux+guy*uy+guz*uz;
    float* dd=d_dd+((size_t)bn*ND+s)*3;
    dd[0]=(gux-gd*ux)*inv_r+gr*ux;
    dd[1]=(guy-gd*uy)*inv_r+gr*uy;
    dd[2]=(guz-gd*uz)*inv_r+gr*uz;
}

// ---------------- forces ----------------
__global__ void k_force(float* __restrict__ out){
    int bn=blockIdx.x;
    int s=threadIdx.x;
    float fx=0.f,fy=0.f,fz=0.f;
    int cnt=d_cnt[bn], rc=d_rcnt[bn];
    if(s<cnt){
        const float* dd=d_dd+((size_t)bn*ND+s)*3;
        fx+=dd[0]; fy+=dd[1]; fz+=dd[2];
    }
    if(s<rc){
        int e=d_redg[bn*NA+s];
        const float* dd=d_dd+(size_t)e*3;
        fx-=dd[0]; fy-=dd[1]; fz-=dd[2];
    }
    __shared__ float rx[128],ry[128],rz[128];
    rx[s]=fx; ry[s]=fy; rz[s]=fz;
    __syncthreads();
    for(int st=64;st>0;st>>=1){
        if(s<st){ rx[s]+=rx[s+st]; ry[s]+=ry[s+st]; rz[s]+=rz[s+st]; }
        __syncthreads();
    }
    if(s==0){
        float* F=out+NB+(size_t)bn*3;
        F[0]=rx[0]; F[1]=ry[0]; F[2]=rz[0];
    }
}

// ---------------- launch ----------------
extern "C" void kernel_launch(void* const* d_in, const int* in_sizes, int n_in,
                              void* d_out, int out_size){
    const int*   z     = (const int*)  d_in[0];
    const float* pos   = (const float*)d_in[1];
    const float* embed = (const float*)d_in[2];
    const float* WA    = (const float*)d_in[3];
    const float* WB    = (const float*)d_in[4];
    const float* W1    = (const float*)d_in[5];
    const float* b1    = (const float*)d_in[6];
    const float* W2    = (const float*)d_in[7];
    const float* W1s   = (const float*)d_in[8];
    const float* b1s   = (const float*)d_in[9];
    const float* W2s   = (const float*)d_in[10];
    const float* w_out = (const float*)d_in[11];
    const float* ebias = (const float*)d_in[12];
    float* out = (float*)d_out;

    k_geom<<<NB*NA,128>>>(pos);
    k_rev <<<NB*NA,128>>>();
    k_init<<<NB*NA,NF>>>(z, embed);

    k_msg  <<<NB*NA,LF>>>(WA+0*NK*NF, WB+0*NK*NF, 0);
    k_node <<<NB*NA,LF>>>(W1+0*3*4096, b1+0*NF, W2+0*3*4096, 0);
    k_msg  <<<NB*NA,LF>>>(WA+1*NK*NF, WB+1*NK*NF, 1);
    k_node <<<NB*NA,LF>>>(W1+1*3*4096, b1+1*NF, W2+1*3*4096, 1);

    k_final_edge<<<NB*NA,LF>>>(WA+2*NK*NF, WB+2*NK*NF);
    k_final_node<<<NB*NA,NF>>>(z, W1s, b1s, W2s, w_out, ebias);
    k_energy    <<<NB,NA>>>(out);

    kb_final_edge<<<NB*NA,LF>>>(WA+2*NK*NF, WB+2*NK*NF);

    kb_node<<<NB*NA,LF>>>(W1+1*3*4096, W2+1*3*4096, 1);
    kb_edge<<<NB*NA,LF>>>(WA+1*NK*NF, WB+1*NK*NF, 1);
    kb_node<<<NB*NA,LF>>>(W1+0*3*4096, W2+0*3*4096, 0);
    kb_edge<<<NB*NA,LF>>>(WA+0*NK*NF, WB+0*NK*NF, 0);

    k_ddisp<<<NB*NA,128>>>(pos);
    k_force<<<NB*NA,128>>>(out);
}

// round 6
// speedup vs baseline: 2.1430x; 1.2364x over previous
#include <cuda_runtime.h>
#include <math.h>

#define NB 8
#define NA 128
#define ND 127
#define NL 9
#define NF 64
#define NK 16
#define LF (NL*NF)       // 576
#define ES 32            // per-edge stride in d_YR/d_gYR: [0..8]=Y, [16..31]=R
#define SQ3f 1.7320508075688772f
#define CUT2 25.0f
#define CH 4             // edge chunk

// ---------------- scratch ----------------
__device__ float d_YR [(size_t)NB*NA*ND*ES];
__device__ float d_gYR[(size_t)NB*NA*ND*ES];
__device__ float d_dd[(size_t)NB*NA*ND*3];
__device__ int   d_cnt [NB*NA];
__device__ int   d_rcnt[NB*NA];
__device__ int   d_nbr [NB*NA*NA];
__device__ int   d_slot[NB*NA*NA];
__device__ int   d_rnbr[NB*NA*NA];
__device__ int   d_redg[NB*NA*NA];
__device__ float d_x0[(size_t)NB*NA*LF];
__device__ float d_x1[(size_t)NB*NA*LF];
__device__ float d_x2[(size_t)NB*NA*LF];
__device__ float d_y1buf[(size_t)NB*NA*LF];
__device__ float d_y2a[(size_t)NB*NA*LF];
__device__ float d_y2b[(size_t)NB*NA*LF];
__device__ float d_yF[NB*NA*NF];
__device__ float d_dh0[NB*NA*NF];
__device__ float d_gxA[(size_t)NB*NA*LF];
__device__ float d_gxB[(size_t)NB*NA*LF];
__device__ float d_gy1[(size_t)NB*NA*LF];
__device__ float d_ae[NB*NA];

__constant__ int   c_deg[9]    = {0,1,1,1,2,2,2,2,2};
__constant__ float c_binom[16] = {1.f,15.f,105.f,455.f,1365.f,3003.f,5005.f,6435.f,
                                  6435.f,5005.f,3003.f,1365.f,455.f,105.f,15.f,1.f};

// ---------------- geometry + compaction + separable basis ----------------
__global__ void k_geom(const float* __restrict__ pos){
    int bn = blockIdx.x; int b=bn/NA, dst=bn%NA;
    int j = threadIdx.x;
    float pdx=pos[(b*NA+dst)*3+0], pdy=pos[(b*NA+dst)*3+1], pdz=pos[(b*NA+dst)*3+2];
    float dx=0.f,dy=0.f,dz=0.f,r2=1.f; bool act=false;
    if(j!=dst){
        dx=pos[(b*NA+j)*3+0]-pdx;
        dy=pos[(b*NA+j)*3+1]-pdy;
        dz=pos[(b*NA+j)*3+2]-pdz;
        r2=dx*dx+dy*dy+dz*dz+1e-12f;
        act = (1.f - r2/CUT2) > 1e-6f;
    }
    unsigned m=__ballot_sync(0xffffffffu, act);
    int wid=j>>5, lane=j&31;
    __shared__ int wcnt[4];
    if(lane==0) wcnt[wid]=__popc(m);
    __syncthreads();
    int basec=0;
    #pragma unroll
    for(int w=0;w<4;w++) if(w<wid) basec+=wcnt[w];
    int slot = basec + __popc(m & ((1u<<lane)-1u));
    if(j==0) d_cnt[bn]=wcnt[0]+wcnt[1]+wcnt[2]+wcnt[3];
    d_slot[bn*NA+j] = act ? slot : -1;
    if(!act) return;
    d_nbr[bn*NA+slot]=j;
    float om = 1.f - r2/CUT2;
    float r=sqrtf(r2), inv=1.f/r;
    float ux=dx*inv, uy=dy*inv, uz=dz*inv;
    float Y[9];
    Y[0]=1.f; Y[1]=ux; Y[2]=uy; Y[3]=uz;
    Y[4]=SQ3f*ux*uy; Y[5]=SQ3f*uy*uz; Y[6]=0.5f*(3.f*uz*uz-1.f);
    Y[7]=SQ3f*ux*uz; Y[8]=0.5f*SQ3f*(ux*ux-uy*uy);
    float w=1.f/(1.f+r), v=1.f-w;
    float cut=expf(1.f-1.f/om);
    float vp[16]; vp[0]=1.f;
    #pragma unroll
    for(int q=1;q<16;q++) vp[q]=vp[q-1]*v;
    float* o = d_YR + ((size_t)bn*ND+slot)*ES;
    #pragma unroll
    for(int l=0;l<9;l++) o[l]=Y[l];
    float wk=1.f;
    #pragma unroll
    for(int k=0;k<16;k++){ o[16+k]=c_binom[k]*wk*vp[15-k]*cut; wk*=w; }
}

__global__ void k_rev(){
    int bn=blockIdx.x; int b=bn/NA, j=bn%NA;
    int i=threadIdx.x;
    int s = (i!=j) ? d_slot[(b*NA+i)*NA + j] : -1;
    bool act = s>=0;
    unsigned m=__ballot_sync(0xffffffffu, act);
    int wid=i>>5, lane=i&31;
    __shared__ int wcnt[4];
    if(lane==0) wcnt[wid]=__popc(m);
    __syncthreads();
    int basec=0;
    #pragma unroll
    for(int w=0;w<4;w++) if(w<wid) basec+=wcnt[w];
    int rslot = basec + __popc(m & ((1u<<lane)-1u));
    if(i==0) d_rcnt[bn]=wcnt[0]+wcnt[1]+wcnt[2]+wcnt[3];
    if(act){
        d_rnbr[bn*NA+rslot]=i;
        d_redg[bn*NA+rslot]=(b*NA+i)*ND + s;
    }
}

// ---------------- init ----------------
__global__ void k_init(const int* __restrict__ z, const float* __restrict__ embed){
    int bn=blockIdx.x; int b=bn/NA, n=bn%NA;
    int f=threadIdx.x;
    float* x=d_x0+(size_t)bn*LF;
    x[f]=embed[z[b*NA+n]*NF+f];
    #pragma unroll
    for(int l=1;l<9;l++) x[l*NF+f]=0.f;
}

// ---------------- forward message (separable) ----------------
__global__ void __launch_bounds__(LF,2) k_msg(const float* __restrict__ WA, const float* __restrict__ WB, int layer){
    int bn=blockIdx.x; int b=bn/NA;
    int t=threadIdx.x, l=t/NF, f=t%NF;
    const float* xin = layer? d_x1 : d_x0;
    __shared__ float sWA[NK*NF], sWB[NK*NF];
    __shared__ float sYR[CH][ES];
    __shared__ float saw[CH][NF], srw[CH][NF];
    __shared__ float sxs[CH][LF];
    __shared__ float sxs0[CH][NF];
    for(int i=t;i<NK*NF;i+=LF){ sWA[i]=WA[i]; sWB[i]=WB[i]; }
    int cnt=d_cnt[bn];
    float acc = xin[(size_t)bn*LF+t];
    for(int base=0;base<cnt;base+=CH){
        __syncthreads();
        if(t<CH*ES){ int c=t>>5, i=t&31;
            if(base+c<cnt) sYR[c][i]=d_YR[((size_t)bn*ND+base+c)*ES+i]; }
        if(layer){
            #pragma unroll
            for(int c=0;c<CH;c++) if(base+c<cnt){
                int src=__ldg(&d_nbr[bn*NA+base+c]);
                sxs[c][t]=xin[((size_t)b*NA+src)*LF+t];
            }
        } else {
            if(t<CH*NF){ int c=t>>6, ff=t&63;
                if(base+c<cnt){
                    int src=__ldg(&d_nbr[bn*NA+base+c]);
                    sxs0[c][ff]=xin[((size_t)b*NA+src)*LF+ff];
                }
            }
        }
        __syncthreads();
        if(l<8){
            int c=l&3; bool isa=l<4;
            if(base+c<cnt){
                const float* Wp = isa? sWA : sWB;
                float s=0.f;
                #pragma unroll
                for(int k=0;k<NK;k++) s=fmaf(sYR[c][16+k],Wp[k*NF+f],s);
                if(isa) saw[c][f]=s; else srw[c][f]=s;
            }
        }
        __syncthreads();
        #pragma unroll
        for(int c=0;c<CH;c++) if(base+c<cnt){
            float xs0 = layer? sxs[c][f] : sxs0[c][f];
            acc = fmaf(sYR[c][l], saw[c][f]*xs0, acc);
            if(layer) acc = fmaf(sxs[c][t], srw[c][f], acc);
            else if(l==0) acc = fmaf(xs0, srw[c][f], acc);
        }
    }
    d_y1buf[(size_t)bn*LF+t]=acc;
}

// ---------------- node update ----------------
__global__ void __launch_bounds__(LF,2) k_node(const float* __restrict__ W1, const float* __restrict__ b1,
                       const float* __restrict__ W2, int layer){
    int bn=blockIdx.x;
    int t=threadIdx.x, l=t/NF, g=t%NF;
    int deg=c_deg[l];
    const float* xin = layer? d_x1 : d_x0;
    float* xout = layer? d_x2 : d_x1;
    float* y2out= layer? d_y2b : d_y2a;
    __shared__ float sy1[LF], sy2[LF], sy3[LF];
    size_t base=(size_t)bn*LF;
    sy1[t]=d_y1buf[base+t];
    __syncthreads();
    const float* w1=W1+deg*4096;
    float v=0.f;
    for(int f=0;f<NF;f++) v=fmaf(sy1[l*NF+f],w1[f*NF+g],v);
    if(l==0) v+=b1[g];
    sy2[t]=v; y2out[base+t]=v;
    __syncthreads();
    float s=sy2[g];
    float sig=1.f/(1.f+expf(-s));
    float y3=(l==0)? s*sig : v*sig;
    sy3[t]=y3;
    __syncthreads();
    const float* w2=W2+deg*4096;
    float o=0.f;
    for(int f=0;f<NF;f++) o=fmaf(sy3[l*NF+f],w2[f*NF+g],o);
    xout[base+t]=xin[base+t]+o;
}

// ---------------- final edge forward ----------------
__global__ void __launch_bounds__(LF,2) k_final_edge(const float* __restrict__ WA2, const float* __restrict__ WB2){
    int bn=blockIdx.x; int b=bn/NA;
    int t=threadIdx.x, l=t/NF, f=t%NF;
    __shared__ float sWA[NK*NF], sWB[NK*NF];
    __shared__ float sYR[CH][ES];
    __shared__ float saw[CH][NF], srw[CH][NF];
    __shared__ float sxs[CH][LF];
    __shared__ float sred[LF];
    for(int i=t;i<NK*NF;i+=LF){ sWA[i]=WA2[i]; sWB[i]=WB2[i]; }
    int cnt=d_cnt[bn];
    float acc=0.f;
    for(int base=0;base<cnt;base+=CH){
        __syncthreads();
        if(t<CH*ES){ int c=t>>5, i=t&31;
            if(base+c<cnt) sYR[c][i]=d_YR[((size_t)bn*ND+base+c)*ES+i]; }
        #pragma unroll
        for(int c=0;c<CH;c++) if(base+c<cnt){
            int src=__ldg(&d_nbr[bn*NA+base+c]);
            sxs[c][t]=d_x2[((size_t)b*NA+src)*LF+t];
        }
        __syncthreads();
        if(l<8){
            int c=l&3; bool isa=l<4;
            if(base+c<cnt){
                const float* Wp = isa? sWA : sWB;
                float s=0.f;
                #pragma unroll
                for(int k=0;k<NK;k++) s=fmaf(sYR[c][16+k],Wp[k*NF+f],s);
                if(isa) saw[c][f]=s; else srw[c][f]=s;
            }
        }
        __syncthreads();
        #pragma unroll
        for(int c=0;c<CH;c++) if(base+c<cnt){
            acc = fmaf(sxs[c][t]*sYR[c][l], srw[c][f], acc);  // mB
            if(l==0) acc = fmaf(saw[c][f], sxs[c][f], acc);   // mA
        }
    }
    __syncthreads();
    sred[t]=acc;
    __syncthreads();
    if(l==0){
        float ss=0.f;
        #pragma unroll
        for(int l2=0;l2<NL;l2++) ss+=sred[l2*NF+f];
        d_yF[bn*NF+f]=ss;
    }
}

// ---------------- final node fwd+bwd ----------------
__global__ void k_final_node(const int* __restrict__ z,
                             const float* __restrict__ W1s, const float* __restrict__ b1s,
                             const float* __restrict__ W2s, const float* __restrict__ w_out,
                             const float* __restrict__ ebias){
    int bn=blockIdx.x; int b=bn/NA, n=bn%NA;
    int f=threadIdx.x;
    __shared__ float sh0[NF], sq[NF], sdp[NF], sred[NF];
    size_t base=(size_t)bn*LF;
    float x0=d_x2[base+f];
    float h0=x0+d_yF[bn*NF+f];
    sh0[f]=h0; __syncthreads();
    float p=b1s[f];
    for(int g=0;g<NF;g++) p=fmaf(sh0[g],W1s[g*NF+f],p);
    float sig=1.f/(1.f+expf(-p));
    float q=p*sig;
    sq[f]=q; __syncthreads();
    float hh=0.f;
    for(int g=0;g<NF;g++) hh=fmaf(sq[g],W2s[g*NF+f],hh);
    float xo=x0+hh;
    sred[f]=xo*w_out[f]; __syncthreads();
    for(int s=32;s>0;s>>=1){ if(f<s) sred[f]+=sred[f+s]; __syncthreads(); }
    if(f==0) d_ae[bn]=sred[0]+ebias[z[b*NA+n]];
    float dq=0.f;
    for(int g=0;g<NF;g++) dq=fmaf(w_out[g],W2s[f*NF+g],dq);
    float dp=dq*sig*(1.f+p*(1.f-sig));
    sdp[f]=dp; __syncthreads();
    float dh0=0.f;
    for(int g=0;g<NF;g++) dh0=fmaf(sdp[g],W1s[f*NF+g],dh0);
    d_dh0[bn*NF+f]=dh0;
    float* gx=d_gxA+base;
    gx[f]=w_out[f]+dh0;
    #pragma unroll
    for(int l=1;l<9;l++) gx[l*NF+f]=0.f;
}

__global__ void k_energy(float* __restrict__ out){
    int b=blockIdx.x;
    __shared__ float sh[NA];
    sh[threadIdx.x]=d_ae[b*NA+threadIdx.x];
    __syncthreads();
    for(int s=64;s>0;s>>=1){ if(threadIdx.x<s) sh[threadIdx.x]+=sh[threadIdx.x+s]; __syncthreads(); }
    if(threadIdx.x==0) out[b]=sh[0];
}

// ---------------- backward final edge (separable, writes gYR '=') ----------------
__global__ void __launch_bounds__(LF,1) kb_final_edge(const float* __restrict__ WA2, const float* __restrict__ WB2){
    int bn=blockIdx.x; int b=bn/NA;
    int t=threadIdx.x, l=t/NF, f=t%NF;
    int lane=t&31, half=(t>>5)&1;
    __shared__ float sWA[NK*NF], sWB[NK*NF];
    __shared__ float sxj[LF];
    __shared__ float sYR[CH][ES];
    __shared__ float saw[CH][NF], srw[CH][NF];
    __shared__ float sdm[CH][NF];
    __shared__ float sq[CH][NF], sg0[CH][NF];
    __shared__ float sgYp[CH][18];
    for(int i=t;i<NK*NF;i+=LF){ sWA[i]=WA2[i]; sWB[i]=WB2[i]; }
    sxj[t]=d_x2[(size_t)bn*LF+t];
    int rc=d_rcnt[bn];
    float acc=0.f;
    for(int base=0;base<rc;base+=CH){
        __syncthreads();
        if(t<CH*ES){ int c=t>>5, i=t&31;
            if(base+c<rc){ int e=__ldg(&d_redg[bn*NA+base+c]); sYR[c][i]=d_YR[(size_t)e*ES+i]; } }
        if(t<CH*NF){ int c=t>>6, ff=t&63;
            if(base+c<rc){ int idst=__ldg(&d_rnbr[bn*NA+base+c]); sdm[c][ff]=d_dh0[(b*NA+idst)*NF+ff]; } }
        __syncthreads();
        if(l<8){
            int c=l&3; bool isa=l<4;
            if(base+c<rc){
                const float* Wp = isa? sWA : sWB;
                float s=0.f;
                #pragma unroll
                for(int k=0;k<NK;k++) s=fmaf(sYR[c][16+k],Wp[k*NF+f],s);
                if(isa) saw[c][f]=s; else srw[c][f]=s;
            }
        }
        __syncthreads();
        #pragma unroll
        for(int c=0;c<CH;c++){
            bool on = (base+c<rc);
            float v=0.f;
            if(on){
                float dm=sdm[c][f], rwv=srw[c][f], Yl=sYR[c][l];
                acc = fmaf(dm*Yl, rwv, acc);               // gx[l,f] += dm·Y[l]·rwF
                if(l==0) acc = fmaf(dm, saw[c][f], acc);   // gx[0,f] += dm·awF
                v = dm*rwv*sxj[t];                         // gY[l] partial
                if(l==0){
                    float xsY=0.f;
                    #pragma unroll
                    for(int l2=0;l2<NL;l2++) xsY=fmaf(sxj[l2*NF+f],sYR[c][l2],xsY);
                    sq[c][f]=dm*sxj[f];                    // u1 = dm·xs0
                    sg0[c][f]=dm*xsY;                      // u2 = dm·xsY
                }
            }
            #pragma unroll
            for(int off=16;off>0;off>>=1) v+=__shfl_down_sync(0xffffffffu,v,off);
            if(lane==0) sgYp[c][l*2+half]=v;
        }
        __syncthreads();
        if(t<512){
            int c=t>>7, k=(t>>3)&15, j=t&7, fb=j*8;
            if(base+c<rc){
                float s=0.f;
                #pragma unroll
                for(int i=0;i<8;i++)
                    s = fmaf(sq[c][fb+i],sWA[k*NF+fb+i],fmaf(sg0[c][fb+i],sWB[k*NF+fb+i],s));
                #pragma unroll
                for(int off=4;off>0;off>>=1) s+=__shfl_down_sync(0xffffffffu,s,off,8);
                if(j==0){ int e=__ldg(&d_redg[bn*NA+base+c]); d_gYR[(size_t)e*ES+16+k]=s; }
            }
        } else if(t<544){
            int u=t-512, c=u>>3, ll=1+(u&7);
            if(base+c<rc){
                float s=sgYp[c][ll*2]+sgYp[c][ll*2+1];
                int e=__ldg(&d_redg[bn*NA+base+c]); d_gYR[(size_t)e*ES+ll]=s;
            }
        }
    }
    d_gxA[(size_t)bn*LF+t]+=acc;
}

// ---------------- backward node ----------------
__global__ void __launch_bounds__(LF,2) kb_node(const float* __restrict__ W1, const float* __restrict__ W2, int layer){
    int bn=blockIdx.x;
    int t=threadIdx.x, l=t/NF, f=t%NF;
    int deg=c_deg[l];
    const float* gxin=(layer==1)? d_gxA : d_gxB;
    const float* y2  =(layer==1)? d_y2b : d_y2a;
    __shared__ float sgxo[LF], sy2[LF], sgy3[LF], sgy2[LF];
    size_t base=(size_t)bn*LF;
    sgxo[t]=gxin[base+t]; sy2[t]=y2[base+t];
    __syncthreads();
    const float* w2=W2+deg*4096+f*NF;
    float gy3=0.f;
    for(int g=0;g<NF;g++) gy3=fmaf(sgxo[l*NF+g],w2[g],gy3);
    sgy3[t]=gy3;
    __syncthreads();
    float s=sy2[f];
    float sig=1.f/(1.f+expf(-s));
    float gy2;
    if(l==0){
        float a=0.f;
        #pragma unroll
        for(int l2=1;l2<NL;l2++) a=fmaf(sgy3[l2*NF+f],sy2[l2*NF+f],a);
        gy2=gy3*sig*(1.f+s*(1.f-sig))+a*sig*(1.f-sig);
    } else gy2=gy3*sig;
    sgy2[t]=gy2;
    __syncthreads();
    const float* w1=W1+deg*4096+f*NF;
    float gy1=0.f;
    for(int g=0;g<NF;g++) gy1=fmaf(sgy2[l*NF+g],w1[g],gy1);
    d_gy1[base+t]=gy1;
    if(layer==1) d_gxB[base+t]=sgxo[t]+gy1;
}

// ---------------- backward layer edge (separable, gYR '+=') ----------------
__global__ void __launch_bounds__(LF,1) kb_edge(const float* __restrict__ WA, const float* __restrict__ WB, int layer){
    int bn=blockIdx.x; int b=bn/NA;
    int t=threadIdx.x, l=t/NF, f=t%NF;
    int lane=t&31, half=(t>>5)&1;
    const float* xin = layer? d_x1 : d_x0;
    __shared__ float sWA[NK*NF], sWB[NK*NF];
    __shared__ float sxj[LF];
    __shared__ float sYR[CH][ES];
    __shared__ float saw[CH][NF], srw[CH][NF];
    __shared__ float sgm[CH][LF];
    __shared__ float sq[CH][NF], sg0[CH][NF];
    __shared__ float sgYp[CH][18];
    for(int i=t;i<NK*NF;i+=LF){ sWA[i]=WA[i]; sWB[i]=WB[i]; }
    sxj[t]=xin[(size_t)bn*LF+t];
    int rc=d_rcnt[bn];
    float acc=0.f;
    for(int base=0;base<rc;base+=CH){
        __syncthreads();
        if(t<CH*ES){ int c=t>>5, i=t&31;
            if(base+c<rc){ int e=__ldg(&d_redg[bn*NA+base+c]); sYR[c][i]=d_YR[(size_t)e*ES+i]; } }
        #pragma unroll
        for(int c=0;c<CH;c++) if(base+c<rc){
            int idst=__ldg(&d_rnbr[bn*NA+base+c]);
            sgm[c][t]=d_gy1[((size_t)b*NA+idst)*LF+t];
        }
        __syncthreads();
        if(l<8){
            int c=l&3; bool isa=l<4;
            if(base+c<rc){
                const float* Wp = isa? sWA : sWB;
                float s=0.f;
                #pragma unroll
                for(int k=0;k<NK;k++) s=fmaf(sYR[c][16+k],Wp[k*NF+f],s);
                if(isa) saw[c][f]=s; else srw[c][f]=s;
            }
        }
        __syncthreads();
        #pragma unroll
        for(int c=0;c<CH;c++){
            bool on = (base+c<rc);
            float v=0.f;
            if(on){
                float gm=sgm[c][t], awv=saw[c][f], xs0=sxj[f];
                if(layer) acc = fmaf(gm, srw[c][f], acc);    // gx[l,f] += gm·rw
                v = gm*awv*xs0;                              // gY[l] partial
                if(l==0){
                    float gmY=0.f, gs0=0.f;
                    #pragma unroll
                    for(int l2=0;l2<NL;l2++){
                        float g2=sgm[c][l2*NF+f];
                        gmY=fmaf(sYR[c][l2],g2,gmY);
                        gs0=fmaf(g2,sxj[l2*NF+f],gs0);
                    }
                    sq[c][f]=gmY*xs0;
                    sg0[c][f]=gs0;
                    if(layer) acc = fmaf(gmY, awv, acc);     // gx[0,f] += gmY·aw
                }
            }
            #pragma unroll
            for(int off=16;off>0;off>>=1) v+=__shfl_down_sync(0xffffffffu,v,off);
            if(lane==0) sgYp[c][l*2+half]=v;
        }
        __syncthreads();
        if(t<512){
            int c=t>>7, k=(t>>3)&15, j=t&7, fb=j*8;
            if(base+c<rc){
                float s=0.f;
                #pragma unroll
                for(int i=0;i<8;i++)
                    s = fmaf(sq[c][fb+i],sWA[k*NF+fb+i],fmaf(sg0[c][fb+i],sWB[k*NF+fb+i],s));
                #pragma unroll
                for(int off=4;off>0;off>>=1) s+=__shfl_down_sync(0xffffffffu,s,off,8);
                if(j==0){ int e=__ldg(&d_redg[bn*NA+base+c]); d_gYR[(size_t)e*ES+16+k]+=s; }
            }
        } else if(t<544){
            int u=t-512, c=u>>3, ll=1+(u&7);
            if(base+c<rc){
                float s=sgYp[c][ll*2]+sgYp[c][ll*2+1];
                int e=__ldg(&d_redg[bn*NA+base+c]); d_gYR[(size_t)e*ES+ll]+=s;
            }
        }
    }
    if(layer==1) d_gxB[(size_t)bn*LF+t]+=acc;
}

// ---------------- basis geometry backward ----------------
__global__ void k_ddisp(const float* __restrict__ pos){
    int bn=blockIdx.x; int b=bn/NA, dst=bn%NA;
    int s=threadIdx.x;
    if(s>=d_cnt[bn]) return;
    int src=d_nbr[bn*NA+s];
    const float* pd=pos+(b*NA+dst)*3;
    const float* ps=pos+(b*NA+src)*3;
    float dx=ps[0]-pd[0], dy=ps[1]-pd[1], dz=ps[2]-pd[2];
    float r2=dx*dx+dy*dy+dz*dz+1e-12f;
    float r=sqrtf(r2), inv_r=1.f/r;
    float ux=dx*inv_r, uy=dy*inv_r, uz=dz*inv_r;
    float om=1.f-r2/CUT2;
    float cut=expf(1.f-1.f/om);
    float dcut=cut*(-2.f*r/CUT2)/(om*om);
    float w=1.f/(1.f+r), v=1.f-w, dwdr=-w*w;
    float wp[16], vp[16];
    wp[0]=1.f; vp[0]=1.f;
    #pragma unroll
    for(int q=1;q<16;q++){ wp[q]=wp[q-1]*w; vp[q]=vp[q-1]*v; }
    const float* gyr = d_gYR + ((size_t)bn*ND+s)*ES;
    float gr=0.f;
    #pragma unroll
    for(int k=0;k<16;k++){
        float rad=c_binom[k]*wp[k]*vp[15-k];
        float t1=(k>0)  ? k*wp[k-1]*vp[15-k]    : 0.f;
        float t2=(k<15) ? (15-k)*wp[k]*vp[14-k] : 0.f;
        float drd=c_binom[k]*(t1-t2)*dwdr;
        gr = fmaf(gyr[16+k], drd*cut + rad*dcut, gr);
    }
    float gY1=gyr[1],gY2=gyr[2],gY3=gyr[3],gY4=gyr[4],gY5=gyr[5],gY6=gyr[6],gY7=gyr[7],gY8=gyr[8];
    float gux=gY1+SQ3f*(gY4*uy+gY7*uz+gY8*ux);
    float guy=gY2+SQ3f*(gY4*ux+gY5*uz-gY8*uy);
    float guz=gY3+SQ3f*(gY5*uy+gY7*ux)+3.f*gY6*uz;
    float gd=gux*ux+guy*uy+guz*uz;
    float* dd=d_dd+((size_t)bn*ND+s)*3;
    dd[0]=(gux-gd*ux)*inv_r+gr*ux;
    dd[1]=(guy-gd*uy)*inv_r+gr*uy;
    dd[2]=(guz-gd*uz)*inv_r+gr*uz;
}

// ---------------- forces ----------------
__global__ void k_force(float* __restrict__ out){
    int bn=blockIdx.x;
    int s=threadIdx.x;
    float fx=0.f,fy=0.f,fz=0.f;
    int cnt=d_cnt[bn], rc=d_rcnt[bn];
    if(s<cnt){
        const float* dd=d_dd+((size_t)bn*ND+s)*3;
        fx+=dd[0]; fy+=dd[1]; fz+=dd[2];
    }
    if(s<rc){
        int e=d_redg[bn*NA+s];
        const float* dd=d_dd+(size_t)e*3;
        fx-=dd[0]; fy-=dd[1]; fz-=dd[2];
    }
    __shared__ float rx[128],ry[128],rz[128];
    rx[s]=fx; ry[s]=fy; rz[s]=fz;
    __syncthreads();
    for(int st=64;st>0;st>>=1){
        if(s<st){ rx[s]+=rx[s+st]; ry[s]+=ry[s+st]; rz[s]+=rz[s+st]; }
        __syncthreads();
    }
    if(s==0){
        float* F=out+NB+(size_t)bn*3;
        F[0]=rx[0]; F[1]=ry[0]; F[2]=rz[0];
    }
}

// ---------------- launch ----------------
extern "C" void kernel_launch(void* const* d_in, const int* in_sizes, int n_in,
                              void* d_out, int out_size){
    const int*   z     = (const int*)  d_in[0];
    const float* pos   = (const float*)d_in[1];
    const float* embed = (const float*)d_in[2];
    const float* WA    = (const float*)d_in[3];
    const float* WB    = (const float*)d_in[4];
    const float* W1    = (const float*)d_in[5];
    const float* b1    = (const float*)d_in[6];
    const float* W2    = (const float*)d_in[7];
    const float* W1s   = (const float*)d_in[8];
    const float* b1s   = (const float*)d_in[9];
    const float* W2s   = (const float*)d_in[10];
    const float* w_out = (const float*)d_in[11];
    const float* ebias = (const float*)d_in[12];
    float* out = (float*)d_out;

    k_geom<<<NB*NA,128>>>(pos);
    k_rev <<<NB*NA,128>>>();
    k_init<<<NB*NA,NF>>>(z, embed);

    k_msg  <<<NB*NA,LF>>>(WA+0*NK*NF, WB+0*NK*NF, 0);
    k_node <<<NB*NA,LF>>>(W1+0*3*4096, b1+0*NF, W2+0*3*4096, 0);
    k_msg  <<<NB*NA,LF>>>(WA+1*NK*NF, WB+1*NK*NF, 1);
    k_node <<<NB*NA,LF>>>(W1+1*3*4096, b1+1*NF, W2+1*3*4096, 1);

    k_final_edge<<<NB*NA,LF>>>(WA+2*NK*NF, WB+2*NK*NF);
    k_final_node<<<NB*NA,NF>>>(z, W1s, b1s, W2s, w_out, ebias);
    k_energy    <<<NB,NA>>>(out);

    kb_final_edge<<<NB*NA,LF>>>(WA+2*NK*NF, WB+2*NK*NF);

    kb_node<<<NB*NA,LF>>>(W1+1*3*4096, W2+1*3*4096, 1);
    kb_edge<<<NB*NA,LF>>>(WA+1*NK*NF, WB+1*NK*NF, 1);
    kb_node<<<NB*NA,LF>>>(W1+0*3*4096, W2+0*3*4096, 0);
    kb_edge<<<NB*NA,LF>>>(WA+0*NK*NF, WB+0*NK*NF, 0);

    k_ddisp<<<NB*NA,128>>>(pos);
    k_force<<<NB*NA,128>>>(out);
}

// round 7
// speedup vs baseline: 2.3214x; 1.0832x over previous
#include <cuda_runtime.h>
#include <math.h>

#define NB 8
#define NA 128
#define ND 127
#define NL 9
#define NF 64
#define NK 16
#define LF (NL*NF)       // 576
#define ES 32            // per-edge stride in d_YR/d_gYR: [0..8]=Y, [16..31]=R
#define SQ3f 1.7320508075688772f
#define CUT2 25.0f
#define CH 8             // edge chunk

// ---------------- scratch ----------------
__device__ float d_YR [(size_t)NB*NA*ND*ES];
__device__ float d_gYR[(size_t)NB*NA*ND*ES];
__device__ float d_dd[(size_t)NB*NA*ND*3];
__device__ int   d_cnt [NB*NA];
__device__ int   d_rcnt[NB*NA];
__device__ int   d_nbr [NB*NA*NA];
__device__ int   d_slot[NB*NA*NA];
__device__ int   d_rnbr[NB*NA*NA];
__device__ int   d_redg[NB*NA*NA];
__device__ float d_x0[(size_t)NB*NA*LF];
__device__ float d_x1[(size_t)NB*NA*LF];
__device__ float d_x2[(size_t)NB*NA*LF];
__device__ float d_y2a[(size_t)NB*NA*LF];
__device__ float d_y2b[(size_t)NB*NA*LF];
__device__ float d_dh0[NB*NA*NF];
__device__ float d_gxA[(size_t)NB*NA*LF];
__device__ float d_gxB[(size_t)NB*NA*LF];
__device__ float d_gy1[(size_t)NB*NA*LF];
__device__ float d_ae[NB*NA];

__constant__ int   c_deg[9]    = {0,1,1,1,2,2,2,2,2};
__constant__ float c_binom[16] = {1.f,15.f,105.f,455.f,1365.f,3003.f,5005.f,6435.f,
                                  6435.f,5005.f,3003.f,1365.f,455.f,105.f,15.f,1.f};

// ---------------- geometry + compaction + separable basis ----------------
__global__ void k_geom(const float* __restrict__ pos){
    int bn = blockIdx.x; int b=bn/NA, dst=bn%NA;
    int j = threadIdx.x;
    float pdx=pos[(b*NA+dst)*3+0], pdy=pos[(b*NA+dst)*3+1], pdz=pos[(b*NA+dst)*3+2];
    float dx=0.f,dy=0.f,dz=0.f,r2=1.f; bool act=false;
    if(j!=dst){
        dx=pos[(b*NA+j)*3+0]-pdx;
        dy=pos[(b*NA+j)*3+1]-pdy;
        dz=pos[(b*NA+j)*3+2]-pdz;
        r2=dx*dx+dy*dy+dz*dz+1e-12f;
        act = (1.f - r2/CUT2) > 1e-6f;
    }
    unsigned m=__ballot_sync(0xffffffffu, act);
    int wid=j>>5, lane=j&31;
    __shared__ int wcnt[4];
    if(lane==0) wcnt[wid]=__popc(m);
    __syncthreads();
    int basec=0;
    #pragma unroll
    for(int w=0;w<4;w++) if(w<wid) basec+=wcnt[w];
    int slot = basec + __popc(m & ((1u<<lane)-1u));
    if(j==0) d_cnt[bn]=wcnt[0]+wcnt[1]+wcnt[2]+wcnt[3];
    d_slot[bn*NA+j] = act ? slot : -1;
    if(!act) return;
    d_nbr[bn*NA+slot]=j;
    float om = 1.f - r2/CUT2;
    float r=sqrtf(r2), inv=1.f/r;
    float ux=dx*inv, uy=dy*inv, uz=dz*inv;
    float Y[9];
    Y[0]=1.f; Y[1]=ux; Y[2]=uy; Y[3]=uz;
    Y[4]=SQ3f*ux*uy; Y[5]=SQ3f*uy*uz; Y[6]=0.5f*(3.f*uz*uz-1.f);
    Y[7]=SQ3f*ux*uz; Y[8]=0.5f*SQ3f*(ux*ux-uy*uy);
    float w=1.f/(1.f+r), v=1.f-w;
    float cut=expf(1.f-1.f/om);
    float vp[16]; vp[0]=1.f;
    #pragma unroll
    for(int q=1;q<16;q++) vp[q]=vp[q-1]*v;
    float* o = d_YR + ((size_t)bn*ND+slot)*ES;
    #pragma unroll
    for(int l=0;l<9;l++) o[l]=Y[l];
    float wk=1.f;
    #pragma unroll
    for(int k=0;k<16;k++){ o[16+k]=c_binom[k]*wk*vp[15-k]*cut; wk*=w; }
}

__global__ void k_rev(){
    int bn=blockIdx.x; int b=bn/NA, j=bn%NA;
    int i=threadIdx.x;
    int s = (i!=j) ? d_slot[(b*NA+i)*NA + j] : -1;
    bool act = s>=0;
    unsigned m=__ballot_sync(0xffffffffu, act);
    int wid=i>>5, lane=i&31;
    __shared__ int wcnt[4];
    if(lane==0) wcnt[wid]=__popc(m);
    __syncthreads();
    int basec=0;
    #pragma unroll
    for(int w=0;w<4;w++) if(w<wid) basec+=wcnt[w];
    int rslot = basec + __popc(m & ((1u<<lane)-1u));
    if(i==0) d_rcnt[bn]=wcnt[0]+wcnt[1]+wcnt[2]+wcnt[3];
    if(act){
        d_rnbr[bn*NA+rslot]=i;
        d_redg[bn*NA+rslot]=(b*NA+i)*ND + s;
    }
}

// ---------------- init ----------------
__global__ void k_init(const int* __restrict__ z, const float* __restrict__ embed){
    int bn=blockIdx.x; int b=bn/NA, n=bn%NA;
    int f=threadIdx.x;
    float* x=d_x0+(size_t)bn*LF;
    x[f]=embed[z[b*NA+n]*NF+f];
    #pragma unroll
    for(int l=1;l<9;l++) x[l*NF+f]=0.f;
}

// ---------------- fused layer: message + node update ----------------
__global__ void __launch_bounds__(LF,2) k_layer(const float* __restrict__ WA, const float* __restrict__ WB,
                        const float* __restrict__ W1, const float* __restrict__ b1,
                        const float* __restrict__ W2, int layer){
    int bn=blockIdx.x; int b=bn/NA;
    int t=threadIdx.x, l=t/NF, f=t%NF;
    const float* xin = layer? d_x1 : d_x0;
    float* xout = layer? d_x2 : d_x1;
    float* y2out= layer? d_y2b : d_y2a;
    __shared__ float sWA[NK*NF], sWB[NK*NF];
    __shared__ float sYR[CH][ES];
    __shared__ float saw[CH][NF], srw[CH][NF];
    __shared__ float sxs[CH][LF];
    __shared__ float sy[LF];
    for(int i=t;i<NK*NF;i+=LF){ sWA[i]=WA[i]; sWB[i]=WB[i]; }
    int cnt=d_cnt[bn];
    float xv = xin[(size_t)bn*LF+t];
    float acc = xv;
    for(int base=0;base<cnt;base+=CH){
        __syncthreads();
        if(t<CH*ES){ int c=t>>5, i=t&31;
            if(base+c<cnt) sYR[c][i]=d_YR[((size_t)bn*ND+base+c)*ES+i]; }
        if(layer){
            #pragma unroll
            for(int c=0;c<CH;c++) if(base+c<cnt){
                int src=__ldg(&d_nbr[bn*NA+base+c]);
                sxs[c][t]=xin[((size_t)b*NA+src)*LF+t];
            }
        } else {
            if(t<CH*NF){ int c=t>>6, ff=t&63;
                if(base+c<cnt){
                    int src=__ldg(&d_nbr[bn*NA+base+c]);
                    sxs[c][ff]=xin[((size_t)b*NA+src)*LF+ff];
                }
            }
        }
        __syncthreads();
        if(t<CH*NF){
            int c=t>>6, ff=t&63;
            if(base+c<cnt){
                float sa=0.f, sb=0.f;
                #pragma unroll
                for(int k=0;k<NK;k++){
                    float rk=sYR[c][16+k];
                    sa=fmaf(rk,sWA[k*NF+ff],sa);
                    sb=fmaf(rk,sWB[k*NF+ff],sb);
                }
                saw[c][ff]=sa; srw[c][ff]=sb;
            }
        }
        __syncthreads();
        #pragma unroll
        for(int c=0;c<CH;c++) if(base+c<cnt){
            float xs0=sxs[c][f];
            acc = fmaf(sYR[c][l]*saw[c][f], xs0, acc);
            if(layer) acc = fmaf(sxs[c][t], srw[c][f], acc);
            else if(l==0) acc = fmaf(xs0, srw[c][f], acc);
        }
    }
    // node phase
    __syncthreads();
    sy[t]=acc;
    __syncthreads();
    int deg=c_deg[l];
    const float* w1=W1+deg*4096;
    float v=0.f;
    for(int h=0;h<NF;h++) v=fmaf(sy[l*NF+h],w1[h*NF+f],v);
    if(l==0) v+=b1[f];
    y2out[(size_t)bn*LF+t]=v;
    float* sy2=&sxs[0][0]; float* sy3=&sxs[1][0];
    __syncthreads();
    sy2[t]=v;
    __syncthreads();
    float s=sy2[f];
    float sig=1.f/(1.f+expf(-s));
    float y3=(l==0)? s*sig : v*sig;
    sy3[t]=y3;
    __syncthreads();
    const float* w2=W2+deg*4096;
    float o=0.f;
    for(int h=0;h<NF;h++) o=fmaf(sy3[l*NF+h],w2[h*NF+f],o);
    xout[(size_t)bn*LF+t]=xv+o;
}

// ---------------- fused final: edge messages + scalar MLP fwd/bwd ----------------
__global__ void __launch_bounds__(LF,2) k_final(const int* __restrict__ z,
                        const float* __restrict__ WA2, const float* __restrict__ WB2,
                        const float* __restrict__ W1s, const float* __restrict__ b1s,
                        const float* __restrict__ W2s, const float* __restrict__ w_out,
                        const float* __restrict__ ebias){
    int bn=blockIdx.x; int b=bn/NA, n=bn%NA;
    int t=threadIdx.x, l=t/NF, f=t%NF;
    __shared__ float sWA[NK*NF], sWB[NK*NF];
    __shared__ float sYR[CH][ES];
    __shared__ float saw[CH][NF], srw[CH][NF];
    __shared__ float sxs[CH][LF];
    __shared__ float sred[LF];
    __shared__ float sh0[NF], sq[NF], sdp[NF], sdh[NF];
    for(int i=t;i<NK*NF;i+=LF){ sWA[i]=WA2[i]; sWB[i]=WB2[i]; }
    int cnt=d_cnt[bn];
    float acc=0.f;
    for(int base=0;base<cnt;base+=CH){
        __syncthreads();
        if(t<CH*ES){ int c=t>>5, i=t&31;
            if(base+c<cnt) sYR[c][i]=d_YR[((size_t)bn*ND+base+c)*ES+i]; }
        #pragma unroll
        for(int c=0;c<CH;c++) if(base+c<cnt){
            int src=__ldg(&d_nbr[bn*NA+base+c]);
            sxs[c][t]=d_x2[((size_t)b*NA+src)*LF+t];
        }
        __syncthreads();
        if(t<CH*NF){
            int c=t>>6, ff=t&63;
            if(base+c<cnt){
                float sa=0.f, sb=0.f;
                #pragma unroll
                for(int k=0;k<NK;k++){
                    float rk=sYR[c][16+k];
                    sa=fmaf(rk,sWA[k*NF+ff],sa);
                    sb=fmaf(rk,sWB[k*NF+ff],sb);
                }
                saw[c][ff]=sa; srw[c][ff]=sb;
            }
        }
        __syncthreads();
        #pragma unroll
        for(int c=0;c<CH;c++) if(base+c<cnt){
            acc = fmaf(sxs[c][t]*sYR[c][l], srw[c][f], acc);
            if(l==0) acc = fmaf(saw[c][f], sxs[c][f], acc);
        }
    }
    __syncthreads();
    sred[t]=acc;
    __syncthreads();
    size_t base0=(size_t)bn*LF;
    float p=0.f, sig=0.f, x0v=0.f;
    if(t<NF){
        float ss=0.f;
        #pragma unroll
        for(int l2=0;l2<NL;l2++) ss+=sred[l2*NF+t];
        x0v=d_x2[base0+t];
        sh0[t]=x0v+ss;
    }
    __syncthreads();
    if(t<NF){
        p=b1s[t];
        for(int g=0;g<NF;g++) p=fmaf(sh0[g],W1s[g*NF+t],p);
        sig=1.f/(1.f+expf(-p));
        sq[t]=p*sig;
    }
    __syncthreads();
    if(t<NF){
        float hh=0.f;
        for(int g=0;g<NF;g++) hh=fmaf(sq[g],W2s[g*NF+t],hh);
        sred[t]=(x0v+hh)*w_out[t];
        float dq=0.f;
        for(int g=0;g<NF;g++) dq=fmaf(w_out[g],W2s[t*NF+g],dq);
        sdp[t]=dq*sig*(1.f+p*(1.f-sig));
    }
    __syncthreads();
    if(t<NF){
        float dh0=0.f;
        for(int g=0;g<NF;g++) dh0=fmaf(sdp[g],W1s[t*NF+g],dh0);
        d_dh0[bn*NF+t]=dh0;
        sdh[t]=dh0;
    }
    if(t==0){
        float e=0.f;
        #pragma unroll
        for(int i=0;i<NF;i++) e+=sred[i];
        d_ae[bn]=e+ebias[z[b*NA+n]];
    }
    __syncthreads();
    d_gxA[base0+t] = (l==0)? (w_out[f]+sdh[f]) : 0.f;
}

__global__ void k_energy(float* __restrict__ out){
    int b=blockIdx.x;
    __shared__ float sh[NA];
    sh[threadIdx.x]=d_ae[b*NA+threadIdx.x];
    __syncthreads();
    for(int s=64;s>0;s>>=1){ if(threadIdx.x<s) sh[threadIdx.x]+=sh[threadIdx.x+s]; __syncthreads(); }
    if(threadIdx.x==0) out[b]=sh[0];
}

// ---------------- backward final edge (separable, writes gYR '=') ----------------
__global__ void __launch_bounds__(LF,2) kb_final_edge(const float* __restrict__ WA2, const float* __restrict__ WB2){
    int bn=blockIdx.x; int b=bn/NA;
    int t=threadIdx.x, l=t/NF, f=t%NF;
    int lane=t&31, half=(t>>5)&1;
    __shared__ float sWA[NK*NF], sWB[NK*NF];
    __shared__ float sxj[LF];
    __shared__ float sYR[CH][ES];
    __shared__ float saw[CH][NF], srw[CH][NF];
    __shared__ float sdm[CH][NF];
    __shared__ float sq[CH][NF], sg0[CH][NF];
    __shared__ float sgYp[CH][18];
    for(int i=t;i<NK*NF;i+=LF){ sWA[i]=WA2[i]; sWB[i]=WB2[i]; }
    sxj[t]=d_x2[(size_t)bn*LF+t];
    int rc=d_rcnt[bn];
    float acc=0.f;
    for(int base=0;base<rc;base+=CH){
        __syncthreads();
        if(t<CH*ES){ int c=t>>5, i=t&31;
            if(base+c<rc){ int e=__ldg(&d_redg[bn*NA+base+c]); sYR[c][i]=d_YR[(size_t)e*ES+i]; } }
        if(t<CH*NF){ int c=t>>6, ff=t&63;
            if(base+c<rc){ int idst=__ldg(&d_rnbr[bn*NA+base+c]); sdm[c][ff]=d_dh0[(b*NA+idst)*NF+ff]; } }
        __syncthreads();
        if(t<CH*NF){
            int c=t>>6, ff=t&63;
            if(base+c<rc){
                float sa=0.f, sb=0.f;
                #pragma unroll
                for(int k=0;k<NK;k++){
                    float rk=sYR[c][16+k];
                    sa=fmaf(rk,sWA[k*NF+ff],sa);
                    sb=fmaf(rk,sWB[k*NF+ff],sb);
                }
                saw[c][ff]=sa; srw[c][ff]=sb;
            }
        }
        __syncthreads();
        #pragma unroll
        for(int c=0;c<CH;c++){
            bool on = (base+c<rc);
            float v=0.f;
            if(on){
                float dm=sdm[c][f], rwv=srw[c][f], Yl=sYR[c][l];
                acc = fmaf(dm*Yl, rwv, acc);
                if(l==0) acc = fmaf(dm, saw[c][f], acc);
                v = dm*rwv*sxj[t];
                if(l==0){
                    float xsY=0.f;
                    #pragma unroll
                    for(int l2=0;l2<NL;l2++) xsY=fmaf(sxj[l2*NF+f],sYR[c][l2],xsY);
                    sq[c][f]=dm*sxj[f];
                    sg0[c][f]=dm*xsY;
                }
            }
            #pragma unroll
            for(int off=16;off>0;off>>=1) v+=__shfl_down_sync(0xffffffffu,v,off);
            if(lane==0) sgYp[c][l*2+half]=v;
        }
        __syncthreads();
        if(t<512){
            int c=t>>6, rem=t&63, k=rem>>2, j=rem&3, fb=j*16;
            if(base+c<rc){
                float s=0.f;
                #pragma unroll
                for(int i=0;i<16;i++)
                    s=fmaf(sq[c][fb+i],sWA[k*NF+fb+i],fmaf(sg0[c][fb+i],sWB[k*NF+fb+i],s));
                s+=__shfl_down_sync(0xffffffffu,s,2,4);
                s+=__shfl_down_sync(0xffffffffu,s,1,4);
                if(j==0){ int e=__ldg(&d_redg[bn*NA+base+c]); d_gYR[(size_t)e*ES+16+k]=s; }
            }
        } else {
            int u=t-512, c=u>>3, ll=1+(u&7);
            if(base+c<rc){
                float s=sgYp[c][ll*2]+sgYp[c][ll*2+1];
                int e=__ldg(&d_redg[bn*NA+base+c]);
                d_gYR[(size_t)e*ES+ll]=s;
            }
        }
    }
    d_gxA[(size_t)bn*LF+t]+=acc;
}

// ---------------- backward node ----------------
__global__ void __launch_bounds__(LF,2) kb_node(const float* __restrict__ W1, const float* __restrict__ W2, int layer){
    int bn=blockIdx.x;
    int t=threadIdx.x, l=t/NF, f=t%NF;
    int deg=c_deg[l];
    const float* gxin=(layer==1)? d_gxA : d_gxB;
    const float* y2  =(layer==1)? d_y2b : d_y2a;
    __shared__ float sgxo[LF], sy2[LF], sgy3[LF], sgy2[LF];
    size_t base=(size_t)bn*LF;
    sgxo[t]=gxin[base+t]; sy2[t]=y2[base+t];
    __syncthreads();
    const float* w2=W2+deg*4096+f*NF;
    float gy3=0.f;
    for(int g=0;g<NF;g++) gy3=fmaf(sgxo[l*NF+g],w2[g],gy3);
    sgy3[t]=gy3;
    __syncthreads();
    float s=sy2[f];
    float sig=1.f/(1.f+expf(-s));
    float gy2;
    if(l==0){
        float a=0.f;
        #pragma unroll
        for(int l2=1;l2<NL;l2++) a=fmaf(sgy3[l2*NF+f],sy2[l2*NF+f],a);
        gy2=gy3*sig*(1.f+s*(1.f-sig))+a*sig*(1.f-sig);
    } else gy2=gy3*sig;
    sgy2[t]=gy2;
    __syncthreads();
    const float* w1=W1+deg*4096+f*NF;
    float gy1=0.f;
    for(int g=0;g<NF;g++) gy1=fmaf(sgy2[l*NF+g],w1[g],gy1);
    d_gy1[base+t]=gy1;
    if(layer==1) d_gxB[base+t]=sgxo[t]+gy1;
}

// ---------------- backward layer edge (separable, gYR '+=') ----------------
__global__ void __launch_bounds__(LF,2) kb_edge(const float* __restrict__ WA, const float* __restrict__ WB, int layer){
    int bn=blockIdx.x; int b=bn/NA;
    int t=threadIdx.x, l=t/NF, f=t%NF;
    int lane=t&31, half=(t>>5)&1;
    const float* xin = layer? d_x1 : d_x0;
    __shared__ float sWA[NK*NF], sWB[NK*NF];
    __shared__ float sxj[LF];
    __shared__ float sYR[CH][ES];
    __shared__ float saw[CH][NF], srw[CH][NF];
    __shared__ float sgm[CH][LF];
    __shared__ float sq[CH][NF], sg0[CH][NF];
    __shared__ float sgYp[CH][18];
    for(int i=t;i<NK*NF;i+=LF){ sWA[i]=WA[i]; sWB[i]=WB[i]; }
    sxj[t]=xin[(size_t)bn*LF+t];
    int rc=d_rcnt[bn];
    float acc=0.f;
    for(int base=0;base<rc;base+=CH){
        __syncthreads();
        if(t<CH*ES){ int c=t>>5, i=t&31;
            if(base+c<rc){ int e=__ldg(&d_redg[bn*NA+base+c]); sYR[c][i]=d_YR[(size_t)e*ES+i]; } }
        #pragma unroll
        for(int c=0;c<CH;c++) if(base+c<rc){
            int idst=__ldg(&d_rnbr[bn*NA+base+c]);
            sgm[c][t]=d_gy1[((size_t)b*NA+idst)*LF+t];
        }
        __syncthreads();
        if(t<CH*NF){
            int c=t>>6, ff=t&63;
            if(base+c<rc){
                float sa=0.f, sb=0.f;
                #pragma unroll
                for(int k=0;k<NK;k++){
                    float rk=sYR[c][16+k];
                    sa=fmaf(rk,sWA[k*NF+ff],sa);
                    sb=fmaf(rk,sWB[k*NF+ff],sb);
                }
                saw[c][ff]=sa; srw[c][ff]=sb;
            }
        }
        __syncthreads();
        #pragma unroll
        for(int c=0;c<CH;c++){
            bool on = (base+c<rc);
            float v=0.f;
            if(on){
                float gm=sgm[c][t], awv=saw[c][f], xs0=sxj[f];
                if(layer) acc = fmaf(gm, srw[c][f], acc);
                v = gm*awv*xs0;
                if(l==0){
                    float gmY=0.f, gs0=0.f;
                    #pragma unroll
                    for(int l2=0;l2<NL;l2++){
                        float g2=sgm[c][l2*NF+f];
                        gmY=fmaf(sYR[c][l2],g2,gmY);
                        gs0=fmaf(g2,sxj[l2*NF+f],gs0);
                    }
                    sq[c][f]=gmY*xs0;
                    sg0[c][f]=gs0;
                    if(layer) acc = fmaf(gmY, awv, acc);
                }
            }
            #pragma unroll
            for(int off=16;off>0;off>>=1) v+=__shfl_down_sync(0xffffffffu,v,off);
            if(lane==0) sgYp[c][l*2+half]=v;
        }
        __syncthreads();
        if(t<512){
            int c=t>>6, rem=t&63, k=rem>>2, j=rem&3, fb=j*16;
            if(base+c<rc){
                float s=0.f;
                #pragma unroll
                for(int i=0;i<16;i++)
                    s=fmaf(sq[c][fb+i],sWA[k*NF+fb+i],fmaf(sg0[c][fb+i],sWB[k*NF+fb+i],s));
                s+=__shfl_down_sync(0xffffffffu,s,2,4);
                s+=__shfl_down_sync(0xffffffffu,s,1,4);
                if(j==0){ int e=__ldg(&d_redg[bn*NA+base+c]); d_gYR[(size_t)e*ES+16+k]+=s; }
            }
        } else {
            int u=t-512, c=u>>3, ll=1+(u&7);
            if(base+c<rc){
                float s=sgYp[c][ll*2]+sgYp[c][ll*2+1];
                int e=__ldg(&d_redg[bn*NA+base+c]);
                d_gYR[(size_t)e*ES+ll]+=s;
            }
        }
    }
    if(layer==1) d_gxB[(size_t)bn*LF+t]+=acc;
}

// ---------------- basis geometry backward ----------------
__global__ void k_ddisp(const float* __restrict__ pos){
    int bn=blockIdx.x; int b=bn/NA, dst=bn%NA;
    int s=threadIdx.x;
    if(s>=d_cnt[bn]) return;
    int src=d_nbr[bn*NA+s];
    const float* pd=pos+(b*NA+dst)*3;
    const float* ps=pos+(b*NA+src)*3;
    float dx=ps[0]-pd[0], dy=ps[1]-pd[1], dz=ps[2]-pd[2];
    float r2=dx*dx+dy*dy+dz*dz+1e-12f;
    float r=sqrtf(r2), inv_r=1.f/r;
    float ux=dx*inv_r, uy=dy*inv_r, uz=dz*inv_r;
    float om=1.f-r2/CUT2;
    float cut=expf(1.f-1.f/om);
    float dcut=cut*(-2.f*r/CUT2)/(om*om);
    float w=1.f/(1.f+r), v=1.f-w, dwdr=-w*w;
    float wp[16], vp[16];
    wp[0]=1.f; vp[0]=1.f;
    #pragma unroll
    for(int q=1;q<16;q++){ wp[q]=wp[q-1]*w; vp[q]=vp[q-1]*v; }
    const float* gyr = d_gYR + ((size_t)bn*ND+s)*ES;
    float gr=0.f;
    #pragma unroll
    for(int k=0;k<16;k++){
        float rad=c_binom[k]*wp[k]*vp[15-k];
        float t1=(k>0)  ? k*wp[k-1]*vp[15-k]    : 0.f;
        float t2=(k<15) ? (15-k)*wp[k]*vp[14-k] : 0.f;
        float drd=c_binom[k]*(t1-t2)*dwdr;
        gr = fmaf(gyr[16+k], drd*cut + rad*dcut, gr);
    }
    float gY1=gyr[1],gY2=gyr[2],gY3=gyr[3],gY4=gyr[4],gY5=gyr[5],gY6=gyr[6],gY7=gyr[7],gY8=gyr[8];
    float gux=gY1+SQ3f*(gY4*uy+gY7*uz+gY8*ux);
    float guy=gY2+SQ3f*(gY4*ux+gY5*uz-gY8*uy);
    float guz=gY3+SQ3f*(gY5*uy+gY7*ux)+3.f*gY6*uz;
    float gd=gux*ux+guy*uy+guz*uz;
    float* dd=d_dd+((size_t)bn*ND+s)*3;
    dd[0]=(gux-gd*ux)*inv_r+gr*ux;
    dd[1]=(guy-gd*uy)*inv_r+gr*uy;
    dd[2]=(guz-gd*uz)*inv_r+gr*uz;
}

// ---------------- forces ----------------
__global__ void k_force(float* __restrict__ out){
    int bn=blockIdx.x;
    int s=threadIdx.x;
    float fx=0.f,fy=0.f,fz=0.f;
    int cnt=d_cnt[bn], rc=d_rcnt[bn];
    if(s<cnt){
        const float* dd=d_dd+((size_t)bn*ND+s)*3;
        fx+=dd[0]; fy+=dd[1]; fz+=dd[2];
    }
    if(s<rc){
        int e=d_redg[bn*NA+s];
        const float* dd=d_dd+(size_t)e*3;
        fx-=dd[0]; fy-=dd[1]; fz-=dd[2];
    }
    __shared__ float rx[128],ry[128],rz[128];
    rx[s]=fx; ry[s]=fy; rz[s]=fz;
    __syncthreads();
    for(int st=64;st>0;st>>=1){
        if(s<st){ rx[s]+=rx[s+st]; ry[s]+=ry[s+st]; rz[s]+=rz[s+st]; }
        __syncthreads();
    }
    if(s==0){
        float* F=out+NB+(size_t)bn*3;
        F[0]=rx[0]; F[1]=ry[0]; F[2]=rz[0];
    }
}

// ---------------- launch ----------------
extern "C" void kernel_launch(void* const* d_in, const int* in_sizes, int n_in,
                              void* d_out, int out_size){
    const int*   z     = (const int*)  d_in[0];
    const float* pos   = (const float*)d_in[1];
    const float* embed = (const float*)d_in[2];
    const float* WA    = (const float*)d_in[3];
    const float* WB    = (const float*)d_in[4];
    const float* W1    = (const float*)d_in[5];
    const float* b1    = (const float*)d_in[6];
    const float* W2    = (const float*)d_in[7];
    const float* W1s   = (const float*)d_in[8];
    const float* b1s   = (const float*)d_in[9];
    const float* W2s   = (const float*)d_in[10];
    const float* w_out = (const float*)d_in[11];
    const float* ebias = (const float*)d_in[12];
    float* out = (float*)d_out;

    k_geom<<<NB*NA,128>>>(pos);
    k_rev <<<NB*NA,128>>>();
    k_init<<<NB*NA,NF>>>(z, embed);

    k_layer<<<NB*NA,LF>>>(WA+0*NK*NF, WB+0*NK*NF, W1+0*3*4096, b1+0*NF, W2+0*3*4096, 0);
    k_layer<<<NB*NA,LF>>>(WA+1*NK*NF, WB+1*NK*NF, W1+1*3*4096, b1+1*NF, W2+1*3*4096, 1);

    k_final <<<NB*NA,LF>>>(z, WA+2*NK*NF, WB+2*NK*NF, W1s, b1s, W2s, w_out, ebias);
    k_energy<<<NB,NA>>>(out);

    kb_final_edge<<<NB*NA,LF>>>(WA+2*NK*NF, WB+2*NK*NF);

    kb_node<<<NB*NA,LF>>>(W1+1*3*4096, W2+1*3*4096, 1);
    kb_edge<<<NB*NA,LF>>>(WA+1*NK*NF, WB+1*NK*NF, 1);
    kb_node<<<NB*NA,LF>>>(W1+0*3*4096, W2+0*3*4096, 0);
    kb_edge<<<NB*NA,LF>>>(WA+0*NK*NF, WB+0*NK*NF, 0);

    k_ddisp<<<NB*NA,128>>>(pos);
    k_force<<<NB*NA,128>>>(out);
}